// round 11
// baseline (speedup 1.0000x reference)
#include <cuda_runtime.h>
#include <cuda_fp16.h>
#include <stdint.h>
#include <math.h>

#define BB   8192
#define HH   512
#define NCC  8704          // S*(2K+1)
#define EPSK 1e-6f

__device__ __align__(128) __half g_net[(size_t)BB * NCC];   // 143 MB fp16
__device__ __align__(128) __half g_A1[(size_t)BB * 1024];   // [hi|lo]
__device__ __align__(128) __half g_A2[(size_t)BB * 512];    // single fp16
__device__ __align__(128) __half g_B1[(size_t)HH * 512];
__device__ __align__(128) __half g_B2[(size_t)NCC * 512];

// ------------------------------ helpers ------------------------------------
__device__ __forceinline__ uint32_t smem_u32(const void* p) {
    uint32_t a;
    asm("{ .reg .u64 t; cvta.to.shared.u64 t, %1; cvt.u32.u64 %0, t; }" : "=r"(a) : "l"(p));
    return a;
}
#define CP16(dst, src) \
    asm volatile("cp.async.cg.shared.global [%0], [%1], 16;" :: "r"(dst), "l"(src))
#define CP_COMMIT() asm volatile("cp.async.commit_group;" ::: "memory")
#define CP_WAIT1()  asm volatile("cp.async.wait_group 1;" ::: "memory")

__device__ __forceinline__ void ldm_x4(uint32_t* r, uint32_t addr) {
    asm volatile("ldmatrix.sync.aligned.m8n8.x4.shared.b16 {%0,%1,%2,%3}, [%4];"
                 : "=r"(r[0]), "=r"(r[1]), "=r"(r[2]), "=r"(r[3]) : "r"(addr));
}
__device__ __forceinline__ void mma16816(float* c, const uint32_t* a, const uint32_t* b) {
    asm volatile(
        "mma.sync.aligned.m16n8k16.row.col.f32.f16.f16.f32 "
        "{%0,%1,%2,%3}, {%4,%5,%6,%7}, {%8,%9}, {%0,%1,%2,%3};"
        : "+f"(c[0]), "+f"(c[1]), "+f"(c[2]), "+f"(c[3])
        : "r"(a[0]), "r"(a[1]), "r"(a[2]), "r"(a[3]), "r"(b[0]), "r"(b[1]));
}
__device__ __forceinline__ float tanh_acc(float x) {
    float y = fminf(fmaxf(2.0f * x, -60.0f), 60.0f);
    float t = __expf(y);
    return __fdividef(t - 1.0f, t + 1.0f);
}

// ---------------------------------------------------------------------------
// C[m][n] = tanh( sum_k A[m][k]*B[n][k] + bias[n] )
// APASS=2: A stored [hi(512)|lo(512)] fp16, 2 mma passes (fp32-accurate).
// APASS=1: A single fp16, 1 pass. B single fp16 (row stride 512).
// BK: original-k per stage (32 or 64). CTA 128x128, 256 thr, warp 64x32,
// 3-stage cp.async, ONE __syncthreads/iter, 2 CTAs/SM.
// OUT_F16: write fp16 at row stride Ng; else fp32 at row stride Ng.
// ---------------------------------------------------------------------------
template <int APASS, int BK, bool OUT_F16>
__global__ __launch_bounds__(256, 2)
void gemm_tc(const __half* __restrict__ A, const __half* __restrict__ Bm,
             const float* __restrict__ bias, void* __restrict__ Cv, int Ng)
{
    constexpr int BKB   = BK * 2;            // bytes per k-chunk row
    constexpr int ROWP  = BKB + 16;          // padded pitch
    constexpr uint32_t REG  = 128 * ROWP;
    constexpr uint32_t ALOo = REG;           // A-lo region (APASS==2)
    constexpr uint32_t BRGo = APASS * REG;
    constexpr uint32_t STGS = (APASS + 1) * REG;
    constexpr int AROWB = APASS * 1024;      // A global row bytes
    constexpr int TPR   = BKB / 16;          // loader threads per row
    constexpr int RPP   = 256 / TPR;         // rows per loader pass
    constexpr int NPASS = 128 / RPP;
    constexpr int NIT   = 512 / BK;
    constexpr int NKK   = BK / 16;

    extern __shared__ char dyn[];
    const uint32_t dynB = smem_u32(dyn);
    const int tid  = threadIdx.x;
    const int lane = tid & 31, w = tid >> 5;
    const int warp_m = w & 1, warp_n = w >> 1;        // 2 x 4
    const int mBase = blockIdx.y * 128, nBase = blockIdx.x * 128;

    const char* Ag = (const char*)A + (size_t)mBase * AROWB;
    const char* Bg = (const char*)(Bm + (size_t)nBase * 512);

    const int lrow = tid / TPR;
    const int lch  = (tid % TPR) * 16;

#define LOAD_STAGE(c) do {                                                        \
    const uint32_t _s = dynB + ((c) % 3) * STGS;                                  \
    const size_t _kb = (size_t)(c) * BKB;                                         \
    _Pragma("unroll")                                                             \
    for (int _h = 0; _h < NPASS; _h++) {                                          \
        const int _r = lrow + _h * RPP;                                           \
        const size_t _ra = (size_t)_r * AROWB;                                    \
        CP16(_s + _r * ROWP + lch, Ag + _ra + _kb + lch);                         \
        if (APASS == 2)                                                           \
            CP16(_s + ALOo + _r * ROWP + lch, Ag + _ra + 1024 + _kb + lch);       \
        CP16(_s + BRGo + _r * ROWP + lch, Bg + (size_t)_r * 1024 + _kb + lch);    \
    }                                                                             \
} while (0)

    LOAD_STAGE(0); CP_COMMIT();
    LOAD_STAGE(1); CP_COMMIT();

    float acc[4][4][4];
    #pragma unroll
    for (int i = 0; i < 4; i++)
        #pragma unroll
        for (int j = 0; j < 4; j++)
            #pragma unroll
            for (int e = 0; e < 4; e++) acc[i][j][e] = 0.f;

    const int grp = lane >> 3, lr = lane & 7;
    const int a_row = warp_m * 64 + (grp & 1) * 8 + lr;
    const int a_kb  = (grp >> 1) * 16;
    const int b_row = warp_n * 32 + (grp >> 1) * 8 + lr;
    const int b_kb  = (grp & 1) * 16;

    for (int c = 0; c < NIT; c++) {
        CP_WAIT1();               // stage c resident (c+1 in flight)
        __syncthreads();          // buffer (c+2)%3 free (consumed at iter c-1)
        if (c + 2 < NIT) LOAD_STAGE(c + 2);
        CP_COMMIT();              // uniform group count

        const uint32_t st = dynB + (c % 3) * STGS;

        #pragma unroll
        for (int kk = 0; kk < NKK; kk++) {
            const uint32_t ak = kk * 32 + a_kb;
            const uint32_t bk = kk * 32 + b_kb;
            uint32_t ahi[4][4], b[4][2];

            #pragma unroll
            for (int i = 0; i < 4; i++)
                ldm_x4(ahi[i], st + (uint32_t)(a_row + i * 16) * ROWP + ak);
            #pragma unroll
            for (int p = 0; p < 2; p++) {
                uint32_t r[4];
                ldm_x4(r, st + BRGo + (uint32_t)(b_row + p * 16) * ROWP + bk);
                b[p * 2][0] = r[0]; b[p * 2][1] = r[1];
                b[p * 2 + 1][0] = r[2]; b[p * 2 + 1][1] = r[3];
            }
            #pragma unroll
            for (int i = 0; i < 4; i++)
                #pragma unroll
                for (int j = 0; j < 4; j++)
                    mma16816(acc[i][j], ahi[i], b[j]);        // Ahi*B

            if (APASS == 2) {
                uint32_t alo[4][4];
                #pragma unroll
                for (int i = 0; i < 4; i++)
                    ldm_x4(alo[i], st + ALOo + (uint32_t)(a_row + i * 16) * ROWP + ak);
                #pragma unroll
                for (int i = 0; i < 4; i++)
                    #pragma unroll
                    for (int j = 0; j < 4; j++)
                        mma16816(acc[i][j], alo[i], b[j]);    // Alo*B
            }
        }
    }
#undef LOAD_STAGE

    // ---------------- epilogue: tanh(acc + bias) ----------------
    #pragma unroll
    for (int j = 0; j < 4; j++) {
        const int col = nBase + warp_n * 32 + j * 8 + (lane & 3) * 2;
        const float bv0 = bias[col], bv1 = bias[col + 1];
        #pragma unroll
        for (int i = 0; i < 4; i++) {
            const int r0 = mBase + warp_m * 64 + i * 16 + (lane >> 2);
            float t00 = tanh_acc(acc[i][j][0] + bv0);
            float t01 = tanh_acc(acc[i][j][1] + bv1);
            float t10 = tanh_acc(acc[i][j][2] + bv0);
            float t11 = tanh_acc(acc[i][j][3] + bv1);
            if (OUT_F16) {
                __half* O = (__half*)Cv;
                __half2 h0; h0.x = __float2half_rn(t00); h0.y = __float2half_rn(t01);
                __half2 h1; h1.x = __float2half_rn(t10); h1.y = __float2half_rn(t11);
                *(__half2*)&O[(size_t)r0 * Ng + col]       = h0;
                *(__half2*)&O[(size_t)(r0 + 8) * Ng + col] = h1;
            } else {
                float* Cf = (float*)Cv;
                float2 o0, o1;
                o0.x = t00; o0.y = t01; o1.x = t10; o1.y = t11;
                *(float2*)&Cf[(size_t)r0 * Ng + col]       = o0;
                *(float2*)&Cf[(size_t)(r0 + 8) * Ng + col] = o1;
            }
        }
    }
}

// ---------------------------------------------------------------------------
// prep: A1 = [hi | lo] fp16 of (x_a - 0.5)
// ---------------------------------------------------------------------------
__global__ void split_x_kernel(const float* __restrict__ src,
                               __half* __restrict__ dst)
{
    const int idx = blockIdx.x * 256 + threadIdx.x;   // BB*512
    const int b = idx >> 9, s = idx & 511;
    const float v = src[(size_t)b * 1024 + s] - 0.5f;
    const __half hi = __float2half_rn(v);
    __half* d = dst + (size_t)b * 1024;
    d[s] = hi;
    d[512 + s] = __float2half_rn(v - __half2float(hi));
}

// prep: B'[n][k] = fp16(W[k][n])  (transpose, single fp16)
__global__ void wsplit_kernel(const float* __restrict__ W,
                              __half* __restrict__ Bp, int Ncols)
{
    __shared__ float t[32][33];
    const int n0 = blockIdx.x * 32, k0 = blockIdx.y * 32;
    const int tx = threadIdx.x & 31, ty = threadIdx.x >> 5;   // 32 x 8
    #pragma unroll
    for (int j = 0; j < 4; j++)
        t[ty + 8 * j][tx] = W[(size_t)(k0 + ty + 8 * j) * Ncols + n0 + tx];
    __syncthreads();
    #pragma unroll
    for (int j = 0; j < 4; j++) {
        const int n = n0 + ty + 8 * j;
        const int k = k0 + tx;
        Bp[(size_t)n * 512 + k] = __float2half_rn(t[tx][ty + 8 * j]);
    }
}

// ---------------------------------------------------------------------------
// spline epilogue — reads fp16 net
// ---------------------------------------------------------------------------
__global__ __launch_bounds__(512)
void spline_epilogue_kernel(const float* __restrict__ x_input,
                            const float* __restrict__ log_density,
                            const __half* __restrict__ net,
                            float* __restrict__ out)
{
    const int b = blockIdx.x;
    const int s = threadIdx.x;

    const __half* np = net + (size_t)b * NCC + s * 17;
    float v[17];
    #pragma unroll
    for (int j = 0; j < 17; j++) v[j] = __half2float(np[j]);

    float m = v[9];
    #pragma unroll
    for (int j = 10; j < 17; j++) m = fmaxf(m, v[j]);
    float w[8]; float wsum = 0.f;
    #pragma unroll
    for (int j = 0; j < 8; j++) { w[j] = __expf(v[9 + j] - m); wsum += w[j]; }
    const float winv = 1.f / wsum;
    #pragma unroll
    for (int j = 0; j < 8; j++) w[j] *= winv;

    float eh[9];
    #pragma unroll
    for (int j = 0; j < 9; j++) eh[j] = __expf(v[j]);
    float denom = 0.f;
    #pragma unroll
    for (int i = 0; i < 8; i++) denom += 0.5f * w[i] * (eh[i] + eh[i + 1]);
    const float dinv = 1.f / denom;
    float h[9];
    #pragma unroll
    for (int i = 0; i < 9; i++) h[i] = eh[i] * dinv;

    const float xa = x_input[(size_t)b * 1024 + s];
    const float xb = x_input[(size_t)b * 1024 + 512 + s];

    int cnt = (-EPSK < xb) ? 1 : 0;
    float cs = 0.f;
    #pragma unroll
    for (int i = 0; i < 8; i++) { cs += w[i]; cnt += (cs < xb) ? 1 : 0; }
    int k = cnt - 1;
    k = k < 0 ? 0 : (k > 7 ? 7 : k);

    float xk = 0.f, pk = 0.f, wk = 0.f, hk = 0.f, hk1 = 0.f;
    #pragma unroll
    for (int i = 0; i < 8; i++) {
        const float area = 0.5f * w[i] * (h[i] + h[i + 1]);
        if (i < k)  { xk += w[i]; pk += area; }
        if (i == k) { wk = w[i]; hk = h[i]; hk1 = h[i + 1]; }
    }
    if (k == 0) xk = -EPSK;

    const float alpha = (xb - xk) / wk;
    const float phib  = pk + alpha * hk * wk + 0.5f * alpha * alpha * (hk1 - hk) * wk;
    const float lt    = __logf(fmaf(alpha, (hk1 - hk), hk));

    out[(size_t)b * 1024 + s]       = xa;
    out[(size_t)b * 1024 + 512 + s] = phib;

    __shared__ float red[16];
    float sum = lt;
    #pragma unroll
    for (int o = 16; o > 0; o >>= 1) sum += __shfl_xor_sync(0xffffffffu, sum, o);
    const int lane = s & 31, wid = s >> 5;
    if (lane == 0) red[wid] = sum;
    __syncthreads();
    if (s < 16) {
        float t = red[s];
        #pragma unroll
        for (int o = 8; o > 0; o >>= 1) t += __shfl_xor_sync(0xffffu, t, o);
        if (s == 0) out[(size_t)BB * 1024 + b] = log_density[b] - t;
    }
}

// ---------------------------------------------------------------------------
extern "C" void kernel_launch(void* const* d_in, const int* in_sizes, int n_in,
                              void* d_out, int out_size)
{
    const float* x  = (const float*)d_in[0];
    const float* ld = (const float*)d_in[1];
    const float* W1 = (const float*)d_in[2];
    const float* b1 = (const float*)d_in[3];
    const float* W2 = (const float*)d_in[4];
    const float* b2 = (const float*)d_in[5];
    float* out = (float*)d_out;

    __half *net, *A1, *A2, *B1, *B2;
    cudaGetSymbolAddress((void**)&net, g_net);
    cudaGetSymbolAddress((void**)&A1, g_A1);
    cudaGetSymbolAddress((void**)&A2, g_A2);
    cudaGetSymbolAddress((void**)&B1, g_B1);
    cudaGetSymbolAddress((void**)&B2, g_B2);

    const int DS1 = 3 * 3 * 128 * 80;    // APASS=2, BK=32: 92160
    const int DS2 = 3 * 2 * 128 * 144;   // APASS=1, BK=64: 110592
    cudaFuncSetAttribute((const void*)gemm_tc<2, 32, true>,
                         cudaFuncAttributeMaxDynamicSharedMemorySize, DS1);
    cudaFuncSetAttribute((const void*)gemm_tc<1, 64, true>,
                         cudaFuncAttributeMaxDynamicSharedMemorySize, DS2);

    split_x_kernel<<<BB * 512 / 256, 256>>>(x, A1);
    wsplit_kernel<<<dim3(HH / 32, 512 / 32), 256>>>(W1, B1, HH);
    wsplit_kernel<<<dim3(NCC / 32, 512 / 32), 256>>>(W2, B2, NCC);

    // A2 = fp16(tanh((x_a-0.5) @ W1 + b1)) — accurate 2-pass, fp16 out, stride 512
    gemm_tc<2, 32, true><<<dim3(HH / 128, BB / 128), 256, DS1>>>(A1, B1, b1, A2, 512);
    // net(fp16) = tanh(hid @ W2 + b2) — single-pass, BK=64
    gemm_tc<1, 64, true><<<dim3(NCC / 128, BB / 128), 256, DS2>>>(A2, B2, b2, net, NCC);

    spline_epilogue_kernel<<<BB, 512>>>(x, ld, net, out);
}

// round 12
// speedup vs baseline: 1.0300x; 1.0300x over previous
#include <cuda_runtime.h>
#include <cuda_fp16.h>
#include <stdint.h>
#include <math.h>

#define BB   8192
#define HH   512
#define NCC  8704          // S*(2K+1)
#define EPSK 1e-6f

__device__ __align__(128) __half g_net[(size_t)BB * NCC];   // 143 MB fp16
__device__ __align__(128) __half g_A1[(size_t)BB * 512];    // fp16(x_a - 0.5)
__device__ __align__(128) __half g_A2[(size_t)BB * 512];    // fp16(hid)
__device__ __align__(128) __half g_B1[(size_t)HH * 512];
__device__ __align__(128) __half g_B2[(size_t)NCC * 512];

// ------------------------------ helpers ------------------------------------
__device__ __forceinline__ uint32_t smem_u32(const void* p) {
    uint32_t a;
    asm("{ .reg .u64 t; cvta.to.shared.u64 t, %1; cvt.u32.u64 %0, t; }" : "=r"(a) : "l"(p));
    return a;
}
#define CP16(dst, src) \
    asm volatile("cp.async.cg.shared.global [%0], [%1], 16;" :: "r"(dst), "l"(src))
#define CP_COMMIT() asm volatile("cp.async.commit_group;" ::: "memory")
#define CP_WAIT1()  asm volatile("cp.async.wait_group 1;" ::: "memory")

__device__ __forceinline__ void ldm_x4(uint32_t* r, uint32_t addr) {
    asm volatile("ldmatrix.sync.aligned.m8n8.x4.shared.b16 {%0,%1,%2,%3}, [%4];"
                 : "=r"(r[0]), "=r"(r[1]), "=r"(r[2]), "=r"(r[3]) : "r"(addr));
}
__device__ __forceinline__ void mma16816(float* c, const uint32_t* a, const uint32_t* b) {
    asm volatile(
        "mma.sync.aligned.m16n8k16.row.col.f32.f16.f16.f32 "
        "{%0,%1,%2,%3}, {%4,%5,%6,%7}, {%8,%9}, {%0,%1,%2,%3};"
        : "+f"(c[0]), "+f"(c[1]), "+f"(c[2]), "+f"(c[3])
        : "r"(a[0]), "r"(a[1]), "r"(a[2]), "r"(a[3]), "r"(b[0]), "r"(b[1]));
}
__device__ __forceinline__ float tanh_acc(float x) {
    float y = fminf(fmaxf(2.0f * x, -60.0f), 60.0f);
    float t = __expf(y);
    return __fdividef(t - 1.0f, t + 1.0f);
}

// ---------------------------------------------------------------------------
// C(fp16)[m][n] = tanh( sum_k A[m][k]*B[n][k] + bias[n] )  single-pass fp16.
// A,B fp16 row-major (row stride 512 halfs). CTA 128x128, 256 thr, 8 warps
// (2m x 4n), warp tile 64x32, BK=64 original-k, 3-stage cp.async,
// ONE __syncthreads/iter, 2 CTAs/SM. Output row stride Ng (halfs).
// ---------------------------------------------------------------------------
__global__ __launch_bounds__(256, 2)
void gemm_tc(const __half* __restrict__ A, const __half* __restrict__ Bm,
             const float* __restrict__ bias, __half* __restrict__ C, int Ng)
{
    constexpr int BKB  = 128;               // 64 halfs per k-chunk row
    constexpr int ROWP = BKB + 16;          // 144 padded pitch
    constexpr uint32_t REG  = 128 * ROWP;   // 18432
    constexpr uint32_t STGS = 2 * REG;      // 36864 per stage
    constexpr int NIT  = 512 / 64;          // 8
    constexpr int NKK  = 4;

    extern __shared__ char dyn[];
    const uint32_t dynB = smem_u32(dyn);
    const int tid  = threadIdx.x;
    const int lane = tid & 31, w = tid >> 5;
    const int warp_m = w & 1, warp_n = w >> 1;        // 2 x 4
    const int mBase = blockIdx.y * 128, nBase = blockIdx.x * 128;

    const char* Ag = (const char*)(A  + (size_t)mBase * 512);
    const char* Bg = (const char*)(Bm + (size_t)nBase * 512);

    const int lrow = tid >> 3;          // 0..31 (TPR=8)
    const int lch  = (tid & 7) * 16;

#define LOAD_STAGE(c) do {                                                        \
    const uint32_t _s = dynB + ((c) % 3) * STGS;                                  \
    const size_t _kb = (size_t)(c) * BKB;                                         \
    _Pragma("unroll")                                                             \
    for (int _h = 0; _h < 4; _h++) {                                              \
        const int _r = lrow + _h * 32;                                            \
        CP16(_s + _r * ROWP + lch,       Ag + (size_t)_r * 1024 + _kb + lch);     \
        CP16(_s + REG + _r * ROWP + lch, Bg + (size_t)_r * 1024 + _kb + lch);     \
    }                                                                             \
} while (0)

    LOAD_STAGE(0); CP_COMMIT();
    LOAD_STAGE(1); CP_COMMIT();

    float acc[4][4][4];
    #pragma unroll
    for (int i = 0; i < 4; i++)
        #pragma unroll
        for (int j = 0; j < 4; j++)
            #pragma unroll
            for (int e = 0; e < 4; e++) acc[i][j][e] = 0.f;

    const int grp = lane >> 3, lr = lane & 7;
    const int a_row = warp_m * 64 + (grp & 1) * 8 + lr;
    const int a_kb  = (grp >> 1) * 16;
    const int b_row = warp_n * 32 + (grp >> 1) * 8 + lr;
    const int b_kb  = (grp & 1) * 16;

    for (int c = 0; c < NIT; c++) {
        CP_WAIT1();               // stage c resident (c+1 in flight)
        __syncthreads();          // buffer (c+2)%3 free
        if (c + 2 < NIT) LOAD_STAGE(c + 2);
        CP_COMMIT();              // uniform group count

        const uint32_t st = dynB + (c % 3) * STGS;

        #pragma unroll
        for (int kk = 0; kk < NKK; kk++) {
            const uint32_t ak = kk * 32 + a_kb;
            const uint32_t bk = kk * 32 + b_kb;
            uint32_t a[4][4], b[4][2];

            #pragma unroll
            for (int i = 0; i < 4; i++)
                ldm_x4(a[i], st + (uint32_t)(a_row + i * 16) * ROWP + ak);
            #pragma unroll
            for (int p = 0; p < 2; p++) {
                uint32_t r[4];
                ldm_x4(r, st + REG + (uint32_t)(b_row + p * 16) * ROWP + bk);
                b[p * 2][0] = r[0]; b[p * 2][1] = r[1];
                b[p * 2 + 1][0] = r[2]; b[p * 2 + 1][1] = r[3];
            }
            #pragma unroll
            for (int i = 0; i < 4; i++)
                #pragma unroll
                for (int j = 0; j < 4; j++)
                    mma16816(acc[i][j], a[i], b[j]);
        }
    }
#undef LOAD_STAGE

    // ---------------- epilogue: fp16(tanh(acc + bias)) ----------------
    #pragma unroll
    for (int j = 0; j < 4; j++) {
        const int col = nBase + warp_n * 32 + j * 8 + (lane & 3) * 2;
        const float bv0 = bias[col], bv1 = bias[col + 1];
        #pragma unroll
        for (int i = 0; i < 4; i++) {
            const int r0 = mBase + warp_m * 64 + i * 16 + (lane >> 2);
            __half2 h0, h1;
            h0.x = __float2half_rn(tanh_acc(acc[i][j][0] + bv0));
            h0.y = __float2half_rn(tanh_acc(acc[i][j][1] + bv1));
            h1.x = __float2half_rn(tanh_acc(acc[i][j][2] + bv0));
            h1.y = __float2half_rn(tanh_acc(acc[i][j][3] + bv1));
            *(__half2*)&C[(size_t)r0 * Ng + col]       = h0;
            *(__half2*)&C[(size_t)(r0 + 8) * Ng + col] = h1;
        }
    }
}

// ---------------------------------------------------------------------------
// prep: A1 = fp16(x_a - 0.5)
// ---------------------------------------------------------------------------
__global__ void split_x_kernel(const float* __restrict__ src,
                               __half* __restrict__ dst)
{
    const int idx = blockIdx.x * 256 + threadIdx.x;   // BB*512
    const int b = idx >> 9, s = idx & 511;
    dst[(size_t)b * 512 + s] = __float2half_rn(src[(size_t)b * 1024 + s] - 0.5f);
}

// prep: B'[n][k] = fp16(W[k][n])  (transpose)
__global__ void wsplit_kernel(const float* __restrict__ W,
                              __half* __restrict__ Bp, int Ncols)
{
    __shared__ float t[32][33];
    const int n0 = blockIdx.x * 32, k0 = blockIdx.y * 32;
    const int tx = threadIdx.x & 31, ty = threadIdx.x >> 5;   // 32 x 8
    #pragma unroll
    for (int j = 0; j < 4; j++)
        t[ty + 8 * j][tx] = W[(size_t)(k0 + ty + 8 * j) * Ncols + n0 + tx];
    __syncthreads();
    #pragma unroll
    for (int j = 0; j < 4; j++) {
        const int n = n0 + ty + 8 * j;
        const int k = k0 + tx;
        Bp[(size_t)n * 512 + k] = __float2half_rn(t[tx][ty + 8 * j]);
    }
}

// ---------------------------------------------------------------------------
// spline epilogue — fp16 net staged through smem with vectorized loads
// ---------------------------------------------------------------------------
__global__ __launch_bounds__(512)
void spline_epilogue_kernel(const float* __restrict__ x_input,
                            const float* __restrict__ log_density,
                            const __half* __restrict__ net,
                            float* __restrict__ out)
{
    __shared__ __align__(16) __half row[NCC];   // 17408 B
    __shared__ float red[16];

    const int b = blockIdx.x;
    const int s = threadIdx.x;

    // coalesced staging: 1088 uint4 per row
    {
        const uint4* src = (const uint4*)(net + (size_t)b * NCC);
        uint4* dst = (uint4*)row;
        #pragma unroll
        for (int i = 0; i < 2; i++) dst[s + i * 512] = src[s + i * 512];
        if (s < 64) dst[s + 1024] = src[s + 1024];
    }
    __syncthreads();

    float v[17];
    #pragma unroll
    for (int j = 0; j < 17; j++) v[j] = __half2float(row[s * 17 + j]);

    float m = v[9];
    #pragma unroll
    for (int j = 10; j < 17; j++) m = fmaxf(m, v[j]);
    float w[8]; float wsum = 0.f;
    #pragma unroll
    for (int j = 0; j < 8; j++) { w[j] = __expf(v[9 + j] - m); wsum += w[j]; }
    const float winv = 1.f / wsum;
    #pragma unroll
    for (int j = 0; j < 8; j++) w[j] *= winv;

    float eh[9];
    #pragma unroll
    for (int j = 0; j < 9; j++) eh[j] = __expf(v[j]);
    float denom = 0.f;
    #pragma unroll
    for (int i = 0; i < 8; i++) denom += 0.5f * w[i] * (eh[i] + eh[i + 1]);
    const float dinv = 1.f / denom;
    float h[9];
    #pragma unroll
    for (int i = 0; i < 9; i++) h[i] = eh[i] * dinv;

    const float xa = x_input[(size_t)b * 1024 + s];
    const float xb = x_input[(size_t)b * 1024 + 512 + s];

    int cnt = (-EPSK < xb) ? 1 : 0;
    float cs = 0.f;
    #pragma unroll
    for (int i = 0; i < 8; i++) { cs += w[i]; cnt += (cs < xb) ? 1 : 0; }
    int k = cnt - 1;
    k = k < 0 ? 0 : (k > 7 ? 7 : k);

    float xk = 0.f, pk = 0.f, wk = 0.f, hk = 0.f, hk1 = 0.f;
    #pragma unroll
    for (int i = 0; i < 8; i++) {
        const float area = 0.5f * w[i] * (h[i] + h[i + 1]);
        if (i < k)  { xk += w[i]; pk += area; }
        if (i == k) { wk = w[i]; hk = h[i]; hk1 = h[i + 1]; }
    }
    if (k == 0) xk = -EPSK;

    const float alpha = (xb - xk) / wk;
    const float phib  = pk + alpha * hk * wk + 0.5f * alpha * alpha * (hk1 - hk) * wk;
    const float lt    = __logf(fmaf(alpha, (hk1 - hk), hk));

    out[(size_t)b * 1024 + s]       = xa;
    out[(size_t)b * 1024 + 512 + s] = phib;

    float sum = lt;
    #pragma unroll
    for (int o = 16; o > 0; o >>= 1) sum += __shfl_xor_sync(0xffffffffu, sum, o);
    const int lane = s & 31, wid = s >> 5;
    if (lane == 0) red[wid] = sum;
    __syncthreads();
    if (s < 16) {
        float t = red[s];
        #pragma unroll
        for (int o = 8; o > 0; o >>= 1) t += __shfl_xor_sync(0xffffu, t, o);
        if (s == 0) out[(size_t)BB * 1024 + b] = log_density[b] - t;
    }
}

// ---------------------------------------------------------------------------
extern "C" void kernel_launch(void* const* d_in, const int* in_sizes, int n_in,
                              void* d_out, int out_size)
{
    const float* x  = (const float*)d_in[0];
    const float* ld = (const float*)d_in[1];
    const float* W1 = (const float*)d_in[2];
    const float* b1 = (const float*)d_in[3];
    const float* W2 = (const float*)d_in[4];
    const float* b2 = (const float*)d_in[5];
    float* out = (float*)d_out;

    __half *net, *A1, *A2, *B1, *B2;
    cudaGetSymbolAddress((void**)&net, g_net);
    cudaGetSymbolAddress((void**)&A1, g_A1);
    cudaGetSymbolAddress((void**)&A2, g_A2);
    cudaGetSymbolAddress((void**)&B1, g_B1);
    cudaGetSymbolAddress((void**)&B2, g_B2);

    const int DS = 3 * 2 * 128 * 144;   // 110592
    cudaFuncSetAttribute((const void*)gemm_tc,
                         cudaFuncAttributeMaxDynamicSharedMemorySize, DS);

    split_x_kernel<<<BB * 512 / 256, 256>>>(x, A1);
    wsplit_kernel<<<dim3(HH / 32, 512 / 32), 256>>>(W1, B1, HH);
    wsplit_kernel<<<dim3(NCC / 32, 512 / 32), 256>>>(W2, B2, NCC);

    // hid(fp16) = tanh((x_a-0.5) @ W1 + b1)
    gemm_tc<<<dim3(HH / 128, BB / 128), 256, DS>>>(A1, B1, b1, A2, 512);
    // net(fp16) = tanh(hid @ W2 + b2)
    gemm_tc<<<dim3(NCC / 128, BB / 128), 256, DS>>>(A2, B2, b2, net, NCC);

    spline_epilogue_kernel<<<BB, 512>>>(x, ld, net, out);
}

// round 13
// speedup vs baseline: 1.1405x; 1.1073x over previous
#include <cuda_runtime.h>
#include <cuda_fp16.h>
#include <stdint.h>
#include <math.h>

#define BB   8192
#define HH   512
#define NCC  8704          // S*(2K+1)
#define EPSK 1e-6f

__device__ __align__(128) __half g_net[(size_t)BB * NCC];   // 143 MB fp16
__device__ __align__(128) __half g_A1[(size_t)BB * 512];    // fp16(x_a - 0.5)
__device__ __align__(128) __half g_A2[(size_t)BB * 512];    // fp16(hid)
__device__ __align__(128) __half g_B1[(size_t)HH * 512];
__device__ __align__(128) __half g_B2[(size_t)NCC * 512];

// ------------------------------ helpers ------------------------------------
__device__ __forceinline__ uint32_t smem_u32(const void* p) {
    uint32_t a;
    asm("{ .reg .u64 t; cvta.to.shared.u64 t, %1; cvt.u32.u64 %0, t; }" : "=r"(a) : "l"(p));
    return a;
}
#define CP16(dst, src) \
    asm volatile("cp.async.cg.shared.global [%0], [%1], 16;" :: "r"(dst), "l"(src))
#define CP_COMMIT() asm volatile("cp.async.commit_group;" ::: "memory")
#define CP_WAIT1()  asm volatile("cp.async.wait_group 1;" ::: "memory")

__device__ __forceinline__ void ldm_x4(uint32_t* r, uint32_t addr) {
    asm volatile("ldmatrix.sync.aligned.m8n8.x4.shared.b16 {%0,%1,%2,%3}, [%4];"
                 : "=r"(r[0]), "=r"(r[1]), "=r"(r[2]), "=r"(r[3]) : "r"(addr));
}
__device__ __forceinline__ void mma16816(float* c, const uint32_t* a, const uint32_t* b) {
    asm volatile(
        "mma.sync.aligned.m16n8k16.row.col.f32.f16.f16.f32 "
        "{%0,%1,%2,%3}, {%4,%5,%6,%7}, {%8,%9}, {%0,%1,%2,%3};"
        : "+f"(c[0]), "+f"(c[1]), "+f"(c[2]), "+f"(c[3])
        : "r"(a[0]), "r"(a[1]), "r"(a[2]), "r"(a[3]), "r"(b[0]), "r"(b[1]));
}
__device__ __forceinline__ float tanh_acc(float x) {
    float y = fminf(fmaxf(2.0f * x, -60.0f), 60.0f);
    float t = __expf(y);
    return __fdividef(t - 1.0f, t + 1.0f);
}

// ---------------------------------------------------------------------------
// C(fp16)[m][n] = tanh( sum_k A[m][k]*B[n][k] + bias[n] )  single-pass fp16.
// A,B fp16 row-major (row stride 512 halfs). CTA 128x128, 256 thr, 8 warps
// (2m x 4n), warp tile 64x32, BK=64, 3-stage cp.async, ONE barrier/iter,
// 2 CTAs/SM, kk-level fragment DOUBLE BUFFER (ldsm k+1 overlaps HMMA k).
// ---------------------------------------------------------------------------
__global__ __launch_bounds__(256, 2)
void gemm_tc(const __half* __restrict__ A, const __half* __restrict__ Bm,
             const float* __restrict__ bias, __half* __restrict__ C, int Ng)
{
    constexpr int BKB  = 128;               // 64 halfs per k-chunk row
    constexpr int ROWP = BKB + 16;          // 144 padded pitch
    constexpr uint32_t REG  = 128 * ROWP;   // 18432
    constexpr uint32_t STGS = 2 * REG;      // 36864 per stage
    constexpr int NIT  = 512 / 64;          // 8

    extern __shared__ char dyn[];
    const uint32_t dynB = smem_u32(dyn);
    const int tid  = threadIdx.x;
    const int lane = tid & 31, w = tid >> 5;
    const int warp_m = w & 1, warp_n = w >> 1;        // 2 x 4
    const int mBase = blockIdx.y * 128, nBase = blockIdx.x * 128;

    const char* Ag = (const char*)(A  + (size_t)mBase * 512);
    const char* Bg = (const char*)(Bm + (size_t)nBase * 512);

    const int lrow = tid >> 3;          // 0..31 (TPR=8)
    const int lch  = (tid & 7) * 16;

#define LOAD_STAGE(c) do {                                                        \
    const uint32_t _s = dynB + ((c) % 3) * STGS;                                  \
    const size_t _kb = (size_t)(c) * BKB;                                         \
    _Pragma("unroll")                                                             \
    for (int _h = 0; _h < 4; _h++) {                                              \
        const int _r = lrow + _h * 32;                                            \
        CP16(_s + _r * ROWP + lch,       Ag + (size_t)_r * 1024 + _kb + lch);     \
        CP16(_s + REG + _r * ROWP + lch, Bg + (size_t)_r * 1024 + _kb + lch);     \
    }                                                                             \
} while (0)

    LOAD_STAGE(0); CP_COMMIT();
    LOAD_STAGE(1); CP_COMMIT();

    float acc[4][4][4];
    #pragma unroll
    for (int i = 0; i < 4; i++)
        #pragma unroll
        for (int j = 0; j < 4; j++)
            #pragma unroll
            for (int e = 0; e < 4; e++) acc[i][j][e] = 0.f;

    const int grp = lane >> 3, lr = lane & 7;
    const uint32_t aRow = (uint32_t)(warp_m * 64 + (grp & 1) * 8 + lr) * ROWP
                        + (grp >> 1) * 16;
    const uint32_t bRow = REG
                        + (uint32_t)(warp_n * 32 + (grp >> 1) * 8 + lr) * ROWP
                        + (grp & 1) * 16;

    // double-buffered fragments
    uint32_t aF[2][4][4], bF[2][4][2];

#define LDFRAG(kk, bf) do {                                                       \
    const uint32_t _ak = st + (kk) * 32 + aRow;                                   \
    const uint32_t _bk = st + (kk) * 32 + bRow;                                   \
    _Pragma("unroll")                                                             \
    for (int _i = 0; _i < 4; _i++)                                                \
        ldm_x4(aF[bf][_i], _ak + _i * (16 * ROWP));                               \
    _Pragma("unroll")                                                             \
    for (int _p = 0; _p < 2; _p++) {                                              \
        uint32_t _r[4];                                                           \
        ldm_x4(_r, _bk + _p * (16 * ROWP));                                       \
        bF[bf][_p * 2][0] = _r[0]; bF[bf][_p * 2][1] = _r[1];                     \
        bF[bf][_p * 2 + 1][0] = _r[2]; bF[bf][_p * 2 + 1][1] = _r[3];             \
    }                                                                             \
} while (0)

#define DOMMA(bf)                                                                 \
    _Pragma("unroll")                                                             \
    for (int _i = 0; _i < 4; _i++)                                                \
        _Pragma("unroll")                                                         \
        for (int _j = 0; _j < 4; _j++)                                            \
            mma16816(acc[_i][_j], aF[bf][_i], bF[bf][_j]);

    for (int c = 0; c < NIT; c++) {
        CP_WAIT1();               // stage c resident (c+1 in flight)
        __syncthreads();          // buffer (c+2)%3 free
        const uint32_t st = dynB + (c % 3) * STGS;
        LDFRAG(0, 0);             // first frags ahead of cp.async issue
        if (c + 2 < NIT) LOAD_STAGE(c + 2);
        CP_COMMIT();              // uniform group count

        #pragma unroll
        for (int kk = 0; kk < 4; kk++) {
            if (kk < 3) LDFRAG(kk + 1, (kk + 1) & 1);   // overlap with HMMA kk
            DOMMA(kk & 1);
        }
    }
#undef LOAD_STAGE
#undef LDFRAG
#undef DOMMA

    // ---------------- epilogue: fp16(tanh(acc + bias)) ----------------
    #pragma unroll
    for (int j = 0; j < 4; j++) {
        const int col = nBase + warp_n * 32 + j * 8 + (lane & 3) * 2;
        const float bv0 = bias[col], bv1 = bias[col + 1];
        #pragma unroll
        for (int i = 0; i < 4; i++) {
            const int r0 = mBase + warp_m * 64 + i * 16 + (lane >> 2);
            __half2 h0, h1;
            h0.x = __float2half_rn(tanh_acc(acc[i][j][0] + bv0));
            h0.y = __float2half_rn(tanh_acc(acc[i][j][1] + bv1));
            h1.x = __float2half_rn(tanh_acc(acc[i][j][2] + bv0));
            h1.y = __float2half_rn(tanh_acc(acc[i][j][3] + bv1));
            *(__half2*)&C[(size_t)r0 * Ng + col]       = h0;
            *(__half2*)&C[(size_t)(r0 + 8) * Ng + col] = h1;
        }
    }
}

// ---------------------------------------------------------------------------
// prep: A1 = fp16(x_a - 0.5)
// ---------------------------------------------------------------------------
__global__ void split_x_kernel(const float* __restrict__ src,
                               __half* __restrict__ dst)
{
    const int idx = blockIdx.x * 256 + threadIdx.x;   // BB*512
    const int b = idx >> 9, s = idx & 511;
    dst[(size_t)b * 512 + s] = __float2half_rn(src[(size_t)b * 1024 + s] - 0.5f);
}

// prep: B'[n][k] = fp16(W[k][n])  (transpose)
__global__ void wsplit_kernel(const float* __restrict__ W,
                              __half* __restrict__ Bp, int Ncols)
{
    __shared__ float t[32][33];
    const int n0 = blockIdx.x * 32, k0 = blockIdx.y * 32;
    const int tx = threadIdx.x & 31, ty = threadIdx.x >> 5;   // 32 x 8
    #pragma unroll
    for (int j = 0; j < 4; j++)
        t[ty + 8 * j][tx] = W[(size_t)(k0 + ty + 8 * j) * Ncols + n0 + tx];
    __syncthreads();
    #pragma unroll
    for (int j = 0; j < 4; j++) {
        const int n = n0 + ty + 8 * j;
        const int k = k0 + tx;
        Bp[(size_t)n * 512 + k] = __float2half_rn(t[tx][ty + 8 * j]);
    }
}

// ---------------------------------------------------------------------------
// spline epilogue — fp16 net staged through smem with vectorized loads
// ---------------------------------------------------------------------------
__global__ __launch_bounds__(512)
void spline_epilogue_kernel(const float* __restrict__ x_input,
                            const float* __restrict__ log_density,
                            const __half* __restrict__ net,
                            float* __restrict__ out)
{
    __shared__ __align__(16) __half row[NCC];   // 17408 B
    __shared__ float red[16];

    const int b = blockIdx.x;
    const int s = threadIdx.x;

    // coalesced staging: 1088 uint4 per row
    {
        const uint4* src = (const uint4*)(net + (size_t)b * NCC);
        uint4* dst = (uint4*)row;
        #pragma unroll
        for (int i = 0; i < 2; i++) dst[s + i * 512] = src[s + i * 512];
        if (s < 64) dst[s + 1024] = src[s + 1024];
    }
    __syncthreads();

    float v[17];
    #pragma unroll
    for (int j = 0; j < 17; j++) v[j] = __half2float(row[s * 17 + j]);

    float m = v[9];
    #pragma unroll
    for (int j = 10; j < 17; j++) m = fmaxf(m, v[j]);
    float w[8]; float wsum = 0.f;
    #pragma unroll
    for (int j = 0; j < 8; j++) { w[j] = __expf(v[9 + j] - m); wsum += w[j]; }
    const float winv = 1.f / wsum;
    #pragma unroll
    for (int j = 0; j < 8; j++) w[j] *= winv;

    float eh[9];
    #pragma unroll
    for (int j = 0; j < 9; j++) eh[j] = __expf(v[j]);
    float denom = 0.f;
    #pragma unroll
    for (int i = 0; i < 8; i++) denom += 0.5f * w[i] * (eh[i] + eh[i + 1]);
    const float dinv = 1.f / denom;
    float h[9];
    #pragma unroll
    for (int i = 0; i < 9; i++) h[i] = eh[i] * dinv;

    const float xa = x_input[(size_t)b * 1024 + s];
    const float xb = x_input[(size_t)b * 1024 + 512 + s];

    int cnt = (-EPSK < xb) ? 1 : 0;
    float cs = 0.f;
    #pragma unroll
    for (int i = 0; i < 8; i++) { cs += w[i]; cnt += (cs < xb) ? 1 : 0; }
    int k = cnt - 1;
    k = k < 0 ? 0 : (k > 7 ? 7 : k);

    float xk = 0.f, pk = 0.f, wk = 0.f, hk = 0.f, hk1 = 0.f;
    #pragma unroll
    for (int i = 0; i < 8; i++) {
        const float area = 0.5f * w[i] * (h[i] + h[i + 1]);
        if (i < k)  { xk += w[i]; pk += area; }
        if (i == k) { wk = w[i]; hk = h[i]; hk1 = h[i + 1]; }
    }
    if (k == 0) xk = -EPSK;

    const float alpha = (xb - xk) / wk;
    const float phib  = pk + alpha * hk * wk + 0.5f * alpha * alpha * (hk1 - hk) * wk;
    const float lt    = __logf(fmaf(alpha, (hk1 - hk), hk));

    out[(size_t)b * 1024 + s]       = xa;
    out[(size_t)b * 1024 + 512 + s] = phib;

    float sum = lt;
    #pragma unroll
    for (int o = 16; o > 0; o >>= 1) sum += __shfl_xor_sync(0xffffffffu, sum, o);
    const int lane = s & 31, wid = s >> 5;
    if (lane == 0) red[wid] = sum;
    __syncthreads();
    if (s < 16) {
        float t = red[s];
        #pragma unroll
        for (int o = 8; o > 0; o >>= 1) t += __shfl_xor_sync(0xffffu, t, o);
        if (s == 0) out[(size_t)BB * 1024 + b] = log_density[b] - t;
    }
}

// ---------------------------------------------------------------------------
extern "C" void kernel_launch(void* const* d_in, const int* in_sizes, int n_in,
                              void* d_out, int out_size)
{
    const float* x  = (const float*)d_in[0];
    const float* ld = (const float*)d_in[1];
    const float* W1 = (const float*)d_in[2];
    const float* b1 = (const float*)d_in[3];
    const float* W2 = (const float*)d_in[4];
    const float* b2 = (const float*)d_in[5];
    float* out = (float*)d_out;

    __half *net, *A1, *A2, *B1, *B2;
    cudaGetSymbolAddress((void**)&net, g_net);
    cudaGetSymbolAddress((void**)&A1, g_A1);
    cudaGetSymbolAddress((void**)&A2, g_A2);
    cudaGetSymbolAddress((void**)&B1, g_B1);
    cudaGetSymbolAddress((void**)&B2, g_B2);

    const int DS = 3 * 2 * 128 * 144;   // 110592
    cudaFuncSetAttribute((const void*)gemm_tc,
                         cudaFuncAttributeMaxDynamicSharedMemorySize, DS);

    split_x_kernel<<<BB * 512 / 256, 256>>>(x, A1);
    wsplit_kernel<<<dim3(HH / 32, 512 / 32), 256>>>(W1, B1, HH);
    wsplit_kernel<<<dim3(NCC / 32, 512 / 32), 256>>>(W2, B2, NCC);

    // hid(fp16) = tanh((x_a-0.5) @ W1 + b1)
    gemm_tc<<<dim3(HH / 128, BB / 128), 256, DS>>>(A1, B1, b1, A2, 512);
    // net(fp16) = tanh(hid @ W2 + b2)
    gemm_tc<<<dim3(NCC / 128, BB / 128), 256, DS>>>(A2, B2, b2, net, NCC);

    spline_epilogue_kernel<<<BB, 512>>>(x, ld, net, out);
}

// round 14
// speedup vs baseline: 1.1559x; 1.0135x over previous
#include <cuda_runtime.h>
#include <cuda_fp16.h>
#include <stdint.h>
#include <math.h>

#define BB   8192
#define HH   512
#define NCC  8704          // S*(2K+1)
#define EPSK 1e-6f

__device__ __align__(128) __half g_net[(size_t)BB * NCC];   // 143 MB fp16
__device__ __align__(128) __half g_A1[(size_t)BB * 512];    // fp16(x_a - 0.5)
__device__ __align__(128) __half g_A2[(size_t)BB * 512];    // fp16(hid)
__device__ __align__(128) __half g_B1[(size_t)HH * 512];
__device__ __align__(128) __half g_B2[(size_t)NCC * 512];

// ------------------------------ helpers ------------------------------------
__device__ __forceinline__ uint32_t smem_u32(const void* p) {
    uint32_t a;
    asm("{ .reg .u64 t; cvta.to.shared.u64 t, %1; cvt.u32.u64 %0, t; }" : "=r"(a) : "l"(p));
    return a;
}
#define CP16(dst, src) \
    asm volatile("cp.async.cg.shared.global [%0], [%1], 16;" :: "r"(dst), "l"(src))
#define CP_COMMIT() asm volatile("cp.async.commit_group;" ::: "memory")
#define CP_WAIT1()  asm volatile("cp.async.wait_group 1;" ::: "memory")

__device__ __forceinline__ void ldm_x4(uint32_t* r, uint32_t addr) {
    asm volatile("ldmatrix.sync.aligned.m8n8.x4.shared.b16 {%0,%1,%2,%3}, [%4];"
                 : "=r"(r[0]), "=r"(r[1]), "=r"(r[2]), "=r"(r[3]) : "r"(addr));
}
__device__ __forceinline__ void mma16816(float* c, const uint32_t* a, const uint32_t* b) {
    asm volatile(
        "mma.sync.aligned.m16n8k16.row.col.f32.f16.f16.f32 "
        "{%0,%1,%2,%3}, {%4,%5,%6,%7}, {%8,%9}, {%0,%1,%2,%3};"
        : "+f"(c[0]), "+f"(c[1]), "+f"(c[2]), "+f"(c[3])
        : "r"(a[0]), "r"(a[1]), "r"(a[2]), "r"(a[3]), "r"(b[0]), "r"(b[1]));
}
__device__ __forceinline__ float tanh_acc(float x) {
    float y = fminf(fmaxf(2.0f * x, -60.0f), 60.0f);
    float t = __expf(y);
    return __fdividef(t - 1.0f, t + 1.0f);
}

// ---------------------------------------------------------------------------
// C(fp16)[m][n] = tanh( sum_k A[m][k]*B[n][k] + bias[n] )  single-pass fp16.
// A,B fp16 row-major (row stride 512 halfs). CTA 128x128, 256 thr, 8 warps
// (2m x 4n), warp tile 64x32, BK=64, 3-stage cp.async, ONE barrier/iter,
// 2 CTAs/SM, kk-level fragment double buffer, FULLY UNROLLED mainloop.
// ---------------------------------------------------------------------------
__global__ __launch_bounds__(256, 2)
void gemm_tc(const __half* __restrict__ A, const __half* __restrict__ Bm,
             const float* __restrict__ bias, __half* __restrict__ C, int Ng)
{
    constexpr int BKB  = 128;               // 64 halfs per k-chunk row
    constexpr int ROWP = BKB + 16;          // 144 padded pitch
    constexpr uint32_t REG  = 128 * ROWP;   // 18432
    constexpr uint32_t STGS = 2 * REG;      // 36864 per stage
    constexpr int NIT  = 8;                 // 512 / 64

    extern __shared__ char dyn[];
    const uint32_t dynB = smem_u32(dyn);
    const int tid  = threadIdx.x;
    const int lane = tid & 31, w = tid >> 5;
    const int warp_m = w & 1, warp_n = w >> 1;        // 2 x 4
    const int mBase = blockIdx.y * 128, nBase = blockIdx.x * 128;

    const char* Ag = (const char*)(A  + (size_t)mBase * 512);
    const char* Bg = (const char*)(Bm + (size_t)nBase * 512);

    const int lrow = tid >> 3;          // 0..31 (TPR=8)
    const int lch  = (tid & 7) * 16;

#define LOAD_STAGE(c) do {                                                        \
    const uint32_t _s = dynB + ((c) % 3) * STGS;                                  \
    const size_t _kb = (size_t)(c) * BKB;                                         \
    _Pragma("unroll")                                                             \
    for (int _h = 0; _h < 4; _h++) {                                              \
        const int _r = lrow + _h * 32;                                            \
        CP16(_s + _r * ROWP + lch,       Ag + (size_t)_r * 1024 + _kb + lch);     \
        CP16(_s + REG + _r * ROWP + lch, Bg + (size_t)_r * 1024 + _kb + lch);     \
    }                                                                             \
} while (0)

    LOAD_STAGE(0); CP_COMMIT();
    LOAD_STAGE(1); CP_COMMIT();

    float acc[4][4][4];
    #pragma unroll
    for (int i = 0; i < 4; i++)
        #pragma unroll
        for (int j = 0; j < 4; j++)
            #pragma unroll
            for (int e = 0; e < 4; e++) acc[i][j][e] = 0.f;

    const int grp = lane >> 3, lr = lane & 7;
    const uint32_t aRow = (uint32_t)(warp_m * 64 + (grp & 1) * 8 + lr) * ROWP
                        + (grp >> 1) * 16;
    const uint32_t bRow = REG
                        + (uint32_t)(warp_n * 32 + (grp >> 1) * 8 + lr) * ROWP
                        + (grp & 1) * 16;

    // double-buffered fragments
    uint32_t aF[2][4][4], bF[2][4][2];

#define LDFRAG(st, kk, bf) do {                                                   \
    const uint32_t _ak = (st) + (kk) * 32 + aRow;                                 \
    const uint32_t _bk = (st) + (kk) * 32 + bRow;                                 \
    _Pragma("unroll")                                                             \
    for (int _p = 0; _p < 2; _p++) {                                              \
        uint32_t _r[4];                                                           \
        ldm_x4(_r, _bk + _p * (16 * ROWP));                                       \
        bF[bf][_p * 2][0] = _r[0]; bF[bf][_p * 2][1] = _r[1];                     \
        bF[bf][_p * 2 + 1][0] = _r[2]; bF[bf][_p * 2 + 1][1] = _r[3];             \
    }                                                                             \
    _Pragma("unroll")                                                             \
    for (int _i = 0; _i < 4; _i++)                                                \
        ldm_x4(aF[bf][_i], _ak + _i * (16 * ROWP));                               \
} while (0)

#define DOMMA(bf)                                                                 \
    _Pragma("unroll")                                                             \
    for (int _i = 0; _i < 4; _i++)                                                \
        _Pragma("unroll")                                                         \
        for (int _j = 0; _j < 4; _j++)                                            \
            mma16816(acc[_i][_j], aF[bf][_i], bF[bf][_j]);

    #pragma unroll
    for (int c = 0; c < NIT; c++) {
        CP_WAIT1();               // stage c resident (c+1 in flight)
        __syncthreads();          // buffer (c+2)%3 free
        const uint32_t st = dynB + (c % 3) * STGS;
        LDFRAG(st, 0, 0);         // first frags ahead of cp.async issue
        if (c + 2 < NIT) LOAD_STAGE(c + 2);
        CP_COMMIT();              // uniform group count

        #pragma unroll
        for (int kk = 0; kk < 4; kk++) {
            if (kk < 3) LDFRAG(st, kk + 1, (kk + 1) & 1);   // overlap with HMMA kk
            DOMMA(kk & 1);
        }
    }
#undef LOAD_STAGE
#undef LDFRAG
#undef DOMMA

    // ---------------- epilogue: fp16(tanh(acc + bias)) ----------------
    #pragma unroll
    for (int j = 0; j < 4; j++) {
        const int col = nBase + warp_n * 32 + j * 8 + (lane & 3) * 2;
        const float bv0 = bias[col], bv1 = bias[col + 1];
        #pragma unroll
        for (int i = 0; i < 4; i++) {
            const int r0 = mBase + warp_m * 64 + i * 16 + (lane >> 2);
            __half2 h0, h1;
            h0.x = __float2half_rn(tanh_acc(acc[i][j][0] + bv0));
            h0.y = __float2half_rn(tanh_acc(acc[i][j][1] + bv1));
            h1.x = __float2half_rn(tanh_acc(acc[i][j][2] + bv0));
            h1.y = __float2half_rn(tanh_acc(acc[i][j][3] + bv1));
            *(__half2*)&C[(size_t)r0 * Ng + col]       = h0;
            *(__half2*)&C[(size_t)(r0 + 8) * Ng + col] = h1;
        }
    }
}

// ---------------------------------------------------------------------------
// prep: A1 = fp16(x_a - 0.5)
// ---------------------------------------------------------------------------
__global__ void split_x_kernel(const float* __restrict__ src,
                               __half* __restrict__ dst)
{
    const int idx = blockIdx.x * 256 + threadIdx.x;   // over BB*256 (float2)
    const int b = idx >> 8, s2 = idx & 255;
    const float2 v = *(const float2*)&src[(size_t)b * 1024 + s2 * 2];
    __half2 h;
    h.x = __float2half_rn(v.x - 0.5f);
    h.y = __float2half_rn(v.y - 0.5f);
    *(__half2*)&dst[(size_t)b * 512 + s2 * 2] = h;
}

// prep: B'[n][k] = fp16(W[k][n])  (transpose, half2 stores)
__global__ void wsplit_kernel(const float* __restrict__ W,
                              __half* __restrict__ Bp, int Ncols)
{
    __shared__ float t[32][33];
    const int n0 = blockIdx.x * 32, k0 = blockIdx.y * 32;
    const int tx = threadIdx.x & 31, ty = threadIdx.x >> 5;   // 32 x 8
    #pragma unroll
    for (int j = 0; j < 4; j++)
        t[ty + 8 * j][tx] = W[(size_t)(k0 + ty + 8 * j) * Ncols + n0 + tx];
    __syncthreads();
    // each thread now writes 2 consecutive k of one n: 16 threads per n-row
    const int n = n0 + (threadIdx.x >> 4) + ((threadIdx.x & 8) ? 16 : 0);
    // simpler mapping: 256 threads = 32 n x 8 k-pairs... use tx/ty reuse:
    #pragma unroll
    for (int j = 0; j < 4; j++) {
        const int nn = n0 + ty + 8 * j;
        const int k  = k0 + tx;
        Bp[(size_t)nn * 512 + k] = __float2half_rn(t[tx][ty + 8 * j]);
    }
    (void)n;
}

// ---------------------------------------------------------------------------
// spline epilogue — fp16 net staged through smem; b-order REVERSED for L2 hits
// ---------------------------------------------------------------------------
__global__ __launch_bounds__(512)
void spline_epilogue_kernel(const float* __restrict__ x_input,
                            const float* __restrict__ log_density,
                            const __half* __restrict__ net,
                            float* __restrict__ out)
{
    __shared__ __align__(16) __half row[NCC];   // 17408 B
    __shared__ float red[16];

    const int b = BB - 1 - blockIdx.x;          // reversed: read hottest first
    const int s = threadIdx.x;

    {
        const uint4* src = (const uint4*)(net + (size_t)b * NCC);
        uint4* dst = (uint4*)row;
        #pragma unroll
        for (int i = 0; i < 2; i++) dst[s + i * 512] = src[s + i * 512];
        if (s < 64) dst[s + 1024] = src[s + 1024];
    }
    __syncthreads();

    float v[17];
    #pragma unroll
    for (int j = 0; j < 17; j++) v[j] = __half2float(row[s * 17 + j]);

    float m = v[9];
    #pragma unroll
    for (int j = 10; j < 17; j++) m = fmaxf(m, v[j]);
    float w[8]; float wsum = 0.f;
    #pragma unroll
    for (int j = 0; j < 8; j++) { w[j] = __expf(v[9 + j] - m); wsum += w[j]; }
    const float winv = 1.f / wsum;
    #pragma unroll
    for (int j = 0; j < 8; j++) w[j] *= winv;

    float eh[9];
    #pragma unroll
    for (int j = 0; j < 9; j++) eh[j] = __expf(v[j]);
    float denom = 0.f;
    #pragma unroll
    for (int i = 0; i < 8; i++) denom += 0.5f * w[i] * (eh[i] + eh[i + 1]);
    const float dinv = 1.f / denom;
    float h[9];
    #pragma unroll
    for (int i = 0; i < 9; i++) h[i] = eh[i] * dinv;

    const float xa = x_input[(size_t)b * 1024 + s];
    const float xb = x_input[(size_t)b * 1024 + 512 + s];

    int cnt = (-EPSK < xb) ? 1 : 0;
    float cs = 0.f;
    #pragma unroll
    for (int i = 0; i < 8; i++) { cs += w[i]; cnt += (cs < xb) ? 1 : 0; }
    int k = cnt - 1;
    k = k < 0 ? 0 : (k > 7 ? 7 : k);

    float xk = 0.f, pk = 0.f, wk = 0.f, hk = 0.f, hk1 = 0.f;
    #pragma unroll
    for (int i = 0; i < 8; i++) {
        const float area = 0.5f * w[i] * (h[i] + h[i + 1]);
        if (i < k)  { xk += w[i]; pk += area; }
        if (i == k) { wk = w[i]; hk = h[i]; hk1 = h[i + 1]; }
    }
    if (k == 0) xk = -EPSK;

    const float alpha = (xb - xk) / wk;
    const float phib  = pk + alpha * hk * wk + 0.5f * alpha * alpha * (hk1 - hk) * wk;
    const float lt    = __logf(fmaf(alpha, (hk1 - hk), hk));

    out[(size_t)b * 1024 + s]       = xa;
    out[(size_t)b * 1024 + 512 + s] = phib;

    float sum = lt;
    #pragma unroll
    for (int o = 16; o > 0; o >>= 1) sum += __shfl_xor_sync(0xffffffffu, sum, o);
    const int lane = s & 31, wid = s >> 5;
    if (lane == 0) red[wid] = sum;
    __syncthreads();
    if (s < 16) {
        float t = red[s];
        #pragma unroll
        for (int o = 8; o > 0; o >>= 1) t += __shfl_xor_sync(0xffffu, t, o);
        if (s == 0) out[(size_t)BB * 1024 + b] = log_density[b] - t;
    }
}

// ---------------------------------------------------------------------------
extern "C" void kernel_launch(void* const* d_in, const int* in_sizes, int n_in,
                              void* d_out, int out_size)
{
    const float* x  = (const float*)d_in[0];
    const float* ld = (const float*)d_in[1];
    const float* W1 = (const float*)d_in[2];
    const float* b1 = (const float*)d_in[3];
    const float* W2 = (const float*)d_in[4];
    const float* b2 = (const float*)d_in[5];
    float* out = (float*)d_out;

    __half *net, *A1, *A2, *B1, *B2;
    cudaGetSymbolAddress((void**)&net, g_net);
    cudaGetSymbolAddress((void**)&A1, g_A1);
    cudaGetSymbolAddress((void**)&A2, g_A2);
    cudaGetSymbolAddress((void**)&B1, g_B1);
    cudaGetSymbolAddress((void**)&B2, g_B2);

    const int DS = 3 * 2 * 128 * 144;   // 110592
    cudaFuncSetAttribute((const void*)gemm_tc,
                         cudaFuncAttributeMaxDynamicSharedMemorySize, DS);

    split_x_kernel<<<BB * 256 / 256, 256>>>(x, A1);
    wsplit_kernel<<<dim3(HH / 32, 512 / 32), 256>>>(W1, B1, HH);
    wsplit_kernel<<<dim3(NCC / 32, 512 / 32), 256>>>(W2, B2, NCC);

    // hid(fp16) = tanh((x_a-0.5) @ W1 + b1)
    gemm_tc<<<dim3(HH / 128, BB / 128), 256, DS>>>(A1, B1, b1, A2, 512);
    // net(fp16) = tanh(hid @ W2 + b2)
    gemm_tc<<<dim3(NCC / 128, BB / 128), 256, DS>>>(A2, B2, b2, net, NCC);

    spline_epilogue_kernel<<<BB, 512>>>(x, ld, net, out);
}

// round 15
// speedup vs baseline: 1.1572x; 1.0011x over previous
#include <cuda_runtime.h>
#include <cuda_fp16.h>
#include <stdint.h>
#include <math.h>

#define BB   8192
#define HH   512
#define NCC  8704          // S*(2K+1)
#define EPSK 1e-6f

__device__ __align__(128) __half g_net[(size_t)BB * NCC];   // 143 MB fp16
__device__ __align__(128) __half g_A1[(size_t)BB * 512];    // fp16(x_a - 0.5)
__device__ __align__(128) __half g_A2[(size_t)BB * 512];    // fp16(hid)
__device__ __align__(128) __half g_B1[(size_t)HH * 512];
__device__ __align__(128) __half g_B2[(size_t)NCC * 512];

// ------------------------------ helpers ------------------------------------
__device__ __forceinline__ uint32_t smem_u32(const void* p) {
    uint32_t a;
    asm("{ .reg .u64 t; cvta.to.shared.u64 t, %1; cvt.u32.u64 %0, t; }" : "=r"(a) : "l"(p));
    return a;
}
#define CP16(dst, src) \
    asm volatile("cp.async.cg.shared.global [%0], [%1], 16;" :: "r"(dst), "l"(src))
#define CP16A(dst, src) \
    asm volatile("cp.async.ca.shared.global [%0], [%1], 16;" :: "r"(dst), "l"(src))
#define CP_COMMIT() asm volatile("cp.async.commit_group;" ::: "memory")
#define CP_WAIT1()  asm volatile("cp.async.wait_group 1;" ::: "memory")

__device__ __forceinline__ void ldm_x4(uint32_t* r, uint32_t addr) {
    asm volatile("ldmatrix.sync.aligned.m8n8.x4.shared.b16 {%0,%1,%2,%3}, [%4];"
                 : "=r"(r[0]), "=r"(r[1]), "=r"(r[2]), "=r"(r[3]) : "r"(addr));
}
__device__ __forceinline__ void mma16816(float* c, const uint32_t* a, const uint32_t* b) {
    asm volatile(
        "mma.sync.aligned.m16n8k16.row.col.f32.f16.f16.f32 "
        "{%0,%1,%2,%3}, {%4,%5,%6,%7}, {%8,%9}, {%0,%1,%2,%3};"
        : "+f"(c[0]), "+f"(c[1]), "+f"(c[2]), "+f"(c[3])
        : "r"(a[0]), "r"(a[1]), "r"(a[2]), "r"(a[3]), "r"(b[0]), "r"(b[1]));
}
__device__ __forceinline__ float tanh_acc(float x) {
    float y = fminf(fmaxf(2.0f * x, -60.0f), 60.0f);
    float t = __expf(y);
    return __fdividef(t - 1.0f, t + 1.0f);
}

// ---------------------------------------------------------------------------
// C(fp16)[m][n] = tanh( sum_k A[m][k]*B[n][k] + bias[n] )  single-pass fp16.
// A,B fp16 row-major (row stride 512 halfs). CTA 128x128, 256 thr, 8 warps
// (2m x 4n), warp tile 64x32, BK=64, 3-stage cp.async, ONE barrier/iter,
// 2 CTAs/SM, kk-level fragment double buffer. A loads .ca (cross-CTA L1 reuse).
// ---------------------------------------------------------------------------
__global__ __launch_bounds__(256, 2)
void gemm_tc(const __half* __restrict__ A, const __half* __restrict__ Bm,
             const float* __restrict__ bias, __half* __restrict__ C, int Ng)
{
    constexpr int BKB  = 128;               // 64 halfs per k-chunk row
    constexpr int ROWP = BKB + 16;          // 144 padded pitch
    constexpr uint32_t REG  = 128 * ROWP;   // 18432
    constexpr uint32_t STGS = 2 * REG;      // 36864 per stage
    constexpr int NIT  = 8;                 // 512 / 64

    extern __shared__ char dyn[];
    const uint32_t dynB = smem_u32(dyn);
    const int tid  = threadIdx.x;
    const int lane = tid & 31, w = tid >> 5;
    const int warp_m = w & 1, warp_n = w >> 1;        // 2 x 4
    const int mBase = blockIdx.y * 128, nBase = blockIdx.x * 128;

    const char* Ag = (const char*)(A  + (size_t)mBase * 512);
    const char* Bg = (const char*)(Bm + (size_t)nBase * 512);

    const int lrow = tid >> 3;          // 0..31 (TPR=8)
    const int lch  = (tid & 7) * 16;

#define LOAD_STAGE(c) do {                                                        \
    const uint32_t _s = dynB + ((c) % 3) * STGS;                                  \
    const size_t _kb = (size_t)(c) * BKB;                                         \
    _Pragma("unroll")                                                             \
    for (int _h = 0; _h < 4; _h++) {                                              \
        const int _r = lrow + _h * 32;                                            \
        CP16A(_s + _r * ROWP + lch,      Ag + (size_t)_r * 1024 + _kb + lch);     \
        CP16(_s + REG + _r * ROWP + lch, Bg + (size_t)_r * 1024 + _kb + lch);     \
    }                                                                             \
} while (0)

    LOAD_STAGE(0); CP_COMMIT();
    LOAD_STAGE(1); CP_COMMIT();

    float acc[4][4][4];
    #pragma unroll
    for (int i = 0; i < 4; i++)
        #pragma unroll
        for (int j = 0; j < 4; j++)
            #pragma unroll
            for (int e = 0; e < 4; e++) acc[i][j][e] = 0.f;

    const int grp = lane >> 3, lr = lane & 7;
    const uint32_t aRow = (uint32_t)(warp_m * 64 + (grp & 1) * 8 + lr) * ROWP
                        + (grp >> 1) * 16;
    const uint32_t bRow = REG
                        + (uint32_t)(warp_n * 32 + (grp >> 1) * 8 + lr) * ROWP
                        + (grp & 1) * 16;

    uint32_t aF[2][4][4], bF[2][4][2];

#define LDFRAG(st, kk, bf) do {                                                   \
    const uint32_t _ak = (st) + (kk) * 32 + aRow;                                 \
    const uint32_t _bk = (st) + (kk) * 32 + bRow;                                 \
    _Pragma("unroll")                                                             \
    for (int _p = 0; _p < 2; _p++) {                                              \
        uint32_t _r[4];                                                           \
        ldm_x4(_r, _bk + _p * (16 * ROWP));                                       \
        bF[bf][_p * 2][0] = _r[0]; bF[bf][_p * 2][1] = _r[1];                     \
        bF[bf][_p * 2 + 1][0] = _r[2]; bF[bf][_p * 2 + 1][1] = _r[3];             \
    }                                                                             \
    _Pragma("unroll")                                                             \
    for (int _i = 0; _i < 4; _i++)                                                \
        ldm_x4(aF[bf][_i], _ak + _i * (16 * ROWP));                               \
} while (0)

#define DOMMA(bf)                                                                 \
    _Pragma("unroll")                                                             \
    for (int _i = 0; _i < 4; _i++)                                                \
        _Pragma("unroll")                                                         \
        for (int _j = 0; _j < 4; _j++)                                            \
            mma16816(acc[_i][_j], aF[bf][_i], bF[bf][_j]);

    #pragma unroll
    for (int c = 0; c < NIT; c++) {
        CP_WAIT1();
        __syncthreads();
        const uint32_t st = dynB + (c % 3) * STGS;
        LDFRAG(st, 0, 0);
        if (c + 2 < NIT) LOAD_STAGE(c + 2);
        CP_COMMIT();

        #pragma unroll
        for (int kk = 0; kk < 4; kk++) {
            if (kk < 3) LDFRAG(st, kk + 1, (kk + 1) & 1);
            DOMMA(kk & 1);
        }
    }
#undef LOAD_STAGE
#undef LDFRAG
#undef DOMMA

    // ---------------- epilogue: fp16(tanh(acc + bias)) ----------------
    #pragma unroll
    for (int j = 0; j < 4; j++) {
        const int col = nBase + warp_n * 32 + j * 8 + (lane & 3) * 2;
        const float bv0 = bias[col], bv1 = bias[col + 1];
        #pragma unroll
        for (int i = 0; i < 4; i++) {
            const int r0 = mBase + warp_m * 64 + i * 16 + (lane >> 2);
            __half2 h0, h1;
            h0.x = __float2half_rn(tanh_acc(acc[i][j][0] + bv0));
            h0.y = __float2half_rn(tanh_acc(acc[i][j][1] + bv1));
            h1.x = __float2half_rn(tanh_acc(acc[i][j][2] + bv0));
            h1.y = __float2half_rn(tanh_acc(acc[i][j][3] + bv1));
            *(__half2*)&C[(size_t)r0 * Ng + col]       = h0;
            *(__half2*)&C[(size_t)(r0 + 8) * Ng + col] = h1;
        }
    }
}

// ---------------------------------------------------------------------------
// merged prep: blocks [0,8192) split_x; [8192,8448) wsplit B1; [8448,12800) B2
// ---------------------------------------------------------------------------
__global__ __launch_bounds__(256)
void prep_kernel(const float* __restrict__ x,
                 const float* __restrict__ W1, const float* __restrict__ W2,
                 __half* __restrict__ A1, __half* __restrict__ B1,
                 __half* __restrict__ B2)
{
    const int bid = blockIdx.x;
    if (bid < 8192) {
        // split_x: one block per b, 256 threads x 2 cols (half2)
        const int b = bid, s2 = threadIdx.x;
        const float2 v = *(const float2*)&x[(size_t)b * 1024 + s2 * 2];
        __half2 h;
        h.x = __float2half_rn(v.x - 0.5f);
        h.y = __float2half_rn(v.y - 0.5f);
        *(__half2*)&A1[(size_t)b * 512 + s2 * 2] = h;
        return;
    }
    // transpose+convert 32x32 tile of W
    const float* W; __half* Bp; int Ncols, local;
    if (bid < 8192 + 256) { W = W1; Bp = B1; Ncols = HH;  local = bid - 8192; }
    else                  { W = W2; Bp = B2; Ncols = NCC; local = bid - 8448; }
    const int tilesN = Ncols / 32;
    const int n0 = (local % tilesN) * 32, k0 = (local / tilesN) * 32;

    __shared__ float t[32][33];
    const int tx = threadIdx.x & 31, ty = threadIdx.x >> 5;   // 32 x 8
    #pragma unroll
    for (int j = 0; j < 4; j++)
        t[ty + 8 * j][tx] = W[(size_t)(k0 + ty + 8 * j) * Ncols + n0 + tx];
    __syncthreads();
    #pragma unroll
    for (int j = 0; j < 4; j++) {
        const int n = n0 + ty + 8 * j;
        const int k = k0 + tx;
        Bp[(size_t)n * 512 + k] = __float2half_rn(t[tx][ty + 8 * j]);
    }
}

// ---------------------------------------------------------------------------
// spline epilogue — fp16 net staged through smem; b-order reversed for L2 hits
// ---------------------------------------------------------------------------
__global__ __launch_bounds__(512)
void spline_epilogue_kernel(const float* __restrict__ x_input,
                            const float* __restrict__ log_density,
                            const __half* __restrict__ net,
                            float* __restrict__ out)
{
    __shared__ __align__(16) __half row[NCC];   // 17408 B
    __shared__ float red[16];

    const int b = BB - 1 - blockIdx.x;
    const int s = threadIdx.x;

    {
        const uint4* src = (const uint4*)(net + (size_t)b * NCC);
        uint4* dst = (uint4*)row;
        #pragma unroll
        for (int i = 0; i < 2; i++) dst[s + i * 512] = src[s + i * 512];
        if (s < 64) dst[s + 1024] = src[s + 1024];
    }
    __syncthreads();

    float v[17];
    #pragma unroll
    for (int j = 0; j < 17; j++) v[j] = __half2float(row[s * 17 + j]);

    float m = v[9];
    #pragma unroll
    for (int j = 10; j < 17; j++) m = fmaxf(m, v[j]);
    float w[8]; float wsum = 0.f;
    #pragma unroll
    for (int j = 0; j < 8; j++) { w[j] = __expf(v[9 + j] - m); wsum += w[j]; }
    const float winv = 1.f / wsum;
    #pragma unroll
    for (int j = 0; j < 8; j++) w[j] *= winv;

    float eh[9];
    #pragma unroll
    for (int j = 0; j < 9; j++) eh[j] = __expf(v[j]);
    float denom = 0.f;
    #pragma unroll
    for (int i = 0; i < 8; i++) denom += 0.5f * w[i] * (eh[i] + eh[i + 1]);
    const float dinv = 1.f / denom;
    float h[9];
    #pragma unroll
    for (int i = 0; i < 9; i++) h[i] = eh[i] * dinv;

    const float xa = x_input[(size_t)b * 1024 + s];
    const float xb = x_input[(size_t)b * 1024 + 512 + s];

    int cnt = (-EPSK < xb) ? 1 : 0;
    float cs = 0.f;
    #pragma unroll
    for (int i = 0; i < 8; i++) { cs += w[i]; cnt += (cs < xb) ? 1 : 0; }
    int k = cnt - 1;
    k = k < 0 ? 0 : (k > 7 ? 7 : k);

    float xk = 0.f, pk = 0.f, wk = 0.f, hk = 0.f, hk1 = 0.f;
    #pragma unroll
    for (int i = 0; i < 8; i++) {
        const float area = 0.5f * w[i] * (h[i] + h[i + 1]);
        if (i < k)  { xk += w[i]; pk += area; }
        if (i == k) { wk = w[i]; hk = h[i]; hk1 = h[i + 1]; }
    }
    if (k == 0) xk = -EPSK;

    const float alpha = (xb - xk) / wk;
    const float phib  = pk + alpha * hk * wk + 0.5f * alpha * alpha * (hk1 - hk) * wk;
    const float lt    = __logf(fmaf(alpha, (hk1 - hk), hk));

    out[(size_t)b * 1024 + s]       = xa;
    out[(size_t)b * 1024 + 512 + s] = phib;

    float sum = lt;
    #pragma unroll
    for (int o = 16; o > 0; o >>= 1) sum += __shfl_xor_sync(0xffffffffu, sum, o);
    const int lane = s & 31, wid = s >> 5;
    if (lane == 0) red[wid] = sum;
    __syncthreads();
    if (s < 16) {
        float t = red[s];
        #pragma unroll
        for (int o = 8; o > 0; o >>= 1) t += __shfl_xor_sync(0xffffu, t, o);
        if (s == 0) out[(size_t)BB * 1024 + b] = log_density[b] - t;
    }
}

// ---------------------------------------------------------------------------
extern "C" void kernel_launch(void* const* d_in, const int* in_sizes, int n_in,
                              void* d_out, int out_size)
{
    const float* x  = (const float*)d_in[0];
    const float* ld = (const float*)d_in[1];
    const float* W1 = (const float*)d_in[2];
    const float* b1 = (const float*)d_in[3];
    const float* W2 = (const float*)d_in[4];
    const float* b2 = (const float*)d_in[5];
    float* out = (float*)d_out;

    __half *net, *A1, *A2, *B1, *B2;
    cudaGetSymbolAddress((void**)&net, g_net);
    cudaGetSymbolAddress((void**)&A1, g_A1);
    cudaGetSymbolAddress((void**)&A2, g_A2);
    cudaGetSymbolAddress((void**)&B1, g_B1);
    cudaGetSymbolAddress((void**)&B2, g_B2);

    const int DS = 3 * 2 * 128 * 144;   // 110592
    cudaFuncSetAttribute((const void*)gemm_tc,
                         cudaFuncAttributeMaxDynamicSharedMemorySize, DS);

    // merged prep: 8192 split_x + 256 B1-tiles + 4352 B2-tiles
    prep_kernel<<<8192 + 256 + 4352, 256>>>(x, W1, W2, A1, B1, B2);

    // hid(fp16) = tanh((x_a-0.5) @ W1 + b1)
    gemm_tc<<<dim3(HH / 128, BB / 128), 256, DS>>>(A1, B1, b1, A2, 512);
    // net(fp16) = tanh(hid @ W2 + b2)
    gemm_tc<<<dim3(NCC / 128, BB / 128), 256, DS>>>(A2, B2, b2, net, NCC);

    spline_epilogue_kernel<<<BB, 512>>>(x, ld, net, out);
}

// round 16
// speedup vs baseline: 1.1669x; 1.0084x over previous
#include <cuda_runtime.h>
#include <cuda_fp16.h>
#include <stdint.h>
#include <math.h>

#define BB   8192
#define HH   512
#define NCC  8704          // S*(2K+1)
#define EPSK 1e-6f

// net layout PERMUTED: net[b][j*512 + s] = raw_net[b][s*17 + j]
__device__ __align__(128) __half g_net[(size_t)BB * NCC];   // 143 MB fp16
__device__ __align__(128) __half g_A1[(size_t)BB * 512];    // fp16(x_a - 0.5)
__device__ __align__(128) __half g_A2[(size_t)BB * 512];    // fp16(hid)
__device__ __align__(128) __half g_B1[(size_t)HH * 512];
__device__ __align__(128) __half g_B2[(size_t)NCC * 512];   // rows permuted
__device__ __align__(128) float  g_b2p[NCC];                // permuted bias2

// ------------------------------ helpers ------------------------------------
__device__ __forceinline__ uint32_t smem_u32(const void* p) {
    uint32_t a;
    asm("{ .reg .u64 t; cvta.to.shared.u64 t, %1; cvt.u32.u64 %0, t; }" : "=r"(a) : "l"(p));
    return a;
}
#define CP16(dst, src) \
    asm volatile("cp.async.cg.shared.global [%0], [%1], 16;" :: "r"(dst), "l"(src))
#define CP16A(dst, src) \
    asm volatile("cp.async.ca.shared.global [%0], [%1], 16;" :: "r"(dst), "l"(src))
#define CP_COMMIT() asm volatile("cp.async.commit_group;" ::: "memory")
#define CP_WAIT1()  asm volatile("cp.async.wait_group 1;" ::: "memory")

__device__ __forceinline__ void ldm_x4(uint32_t* r, uint32_t addr) {
    asm volatile("ldmatrix.sync.aligned.m8n8.x4.shared.b16 {%0,%1,%2,%3}, [%4];"
                 : "=r"(r[0]), "=r"(r[1]), "=r"(r[2]), "=r"(r[3]) : "r"(addr));
}
__device__ __forceinline__ void mma16816(float* c, const uint32_t* a, const uint32_t* b) {
    asm volatile(
        "mma.sync.aligned.m16n8k16.row.col.f32.f16.f16.f32 "
        "{%0,%1,%2,%3}, {%4,%5,%6,%7}, {%8,%9}, {%0,%1,%2,%3};"
        : "+f"(c[0]), "+f"(c[1]), "+f"(c[2]), "+f"(c[3])
        : "r"(a[0]), "r"(a[1]), "r"(a[2]), "r"(a[3]), "r"(b[0]), "r"(b[1]));
}
__device__ __forceinline__ float tanh_acc(float x) {
    float y = fminf(fmaxf(2.0f * x, -60.0f), 60.0f);
    float t = __expf(y);
    return __fdividef(t - 1.0f, t + 1.0f);
}

// ---------------------------------------------------------------------------
// C(fp16)[m][n] = tanh( sum_k A[m][k]*B[n][k] + bias[n] )  single-pass fp16.
// Same proven R13/14 skeleton: CTA 128x128, 8 warps, warp 64x32, BK=64,
// 3-stage cp.async, one barrier/iter, 2 CTAs/SM, frag double-buffer.
// ---------------------------------------------------------------------------
__global__ __launch_bounds__(256, 2)
void gemm_tc(const __half* __restrict__ A, const __half* __restrict__ Bm,
             const float* __restrict__ bias, __half* __restrict__ C, int Ng)
{
    constexpr int BKB  = 128;
    constexpr int ROWP = BKB + 16;          // 144
    constexpr uint32_t REG  = 128 * ROWP;   // 18432
    constexpr uint32_t STGS = 2 * REG;      // 36864
    constexpr int NIT  = 8;

    extern __shared__ char dyn[];
    const uint32_t dynB = smem_u32(dyn);
    const int tid  = threadIdx.x;
    const int lane = tid & 31, w = tid >> 5;
    const int warp_m = w & 1, warp_n = w >> 1;        // 2 x 4
    const int mBase = blockIdx.y * 128, nBase = blockIdx.x * 128;

    const char* Ag = (const char*)(A  + (size_t)mBase * 512);
    const char* Bg = (const char*)(Bm + (size_t)nBase * 512);

    const int lrow = tid >> 3;
    const int lch  = (tid & 7) * 16;

#define LOAD_STAGE(c) do {                                                        \
    const uint32_t _s = dynB + ((c) % 3) * STGS;                                  \
    const size_t _kb = (size_t)(c) * BKB;                                         \
    _Pragma("unroll")                                                             \
    for (int _h = 0; _h < 4; _h++) {                                              \
        const int _r = lrow + _h * 32;                                            \
        CP16A(_s + _r * ROWP + lch,      Ag + (size_t)_r * 1024 + _kb + lch);     \
        CP16(_s + REG + _r * ROWP + lch, Bg + (size_t)_r * 1024 + _kb + lch);     \
    }                                                                             \
} while (0)

    LOAD_STAGE(0); CP_COMMIT();
    LOAD_STAGE(1); CP_COMMIT();

    float acc[4][4][4];
    #pragma unroll
    for (int i = 0; i < 4; i++)
        #pragma unroll
        for (int j = 0; j < 4; j++)
            #pragma unroll
            for (int e = 0; e < 4; e++) acc[i][j][e] = 0.f;

    const int grp = lane >> 3, lr = lane & 7;
    const uint32_t aRow = (uint32_t)(warp_m * 64 + (grp & 1) * 8 + lr) * ROWP
                        + (grp >> 1) * 16;
    const uint32_t bRow = REG
                        + (uint32_t)(warp_n * 32 + (grp >> 1) * 8 + lr) * ROWP
                        + (grp & 1) * 16;

    uint32_t aF[2][4][4], bF[2][4][2];

#define LDFRAG(st, kk, bf) do {                                                   \
    const uint32_t _ak = (st) + (kk) * 32 + aRow;                                 \
    const uint32_t _bk = (st) + (kk) * 32 + bRow;                                 \
    _Pragma("unroll")                                                             \
    for (int _p = 0; _p < 2; _p++) {                                              \
        uint32_t _r[4];                                                           \
        ldm_x4(_r, _bk + _p * (16 * ROWP));                                       \
        bF[bf][_p * 2][0] = _r[0]; bF[bf][_p * 2][1] = _r[1];                     \
        bF[bf][_p * 2 + 1][0] = _r[2]; bF[bf][_p * 2 + 1][1] = _r[3];             \
    }                                                                             \
    _Pragma("unroll")                                                             \
    for (int _i = 0; _i < 4; _i++)                                                \
        ldm_x4(aF[bf][_i], _ak + _i * (16 * ROWP));                               \
} while (0)

#define DOMMA(bf)                                                                 \
    _Pragma("unroll")                                                             \
    for (int _i = 0; _i < 4; _i++)                                                \
        _Pragma("unroll")                                                         \
        for (int _j = 0; _j < 4; _j++)                                            \
            mma16816(acc[_i][_j], aF[bf][_i], bF[bf][_j]);

    #pragma unroll
    for (int c = 0; c < NIT; c++) {
        CP_WAIT1();
        __syncthreads();
        const uint32_t st = dynB + (c % 3) * STGS;
        LDFRAG(st, 0, 0);
        if (c + 2 < NIT) LOAD_STAGE(c + 2);
        CP_COMMIT();

        #pragma unroll
        for (int kk = 0; kk < 4; kk++) {
            if (kk < 3) LDFRAG(st, kk + 1, (kk + 1) & 1);
            DOMMA(kk & 1);
        }
    }
#undef LOAD_STAGE
#undef LDFRAG
#undef DOMMA

    #pragma unroll
    for (int j = 0; j < 4; j++) {
        const int col = nBase + warp_n * 32 + j * 8 + (lane & 3) * 2;
        const float bv0 = bias[col], bv1 = bias[col + 1];
        #pragma unroll
        for (int i = 0; i < 4; i++) {
            const int r0 = mBase + warp_m * 64 + i * 16 + (lane >> 2);
            __half2 h0, h1;
            h0.x = __float2half_rn(tanh_acc(acc[i][j][0] + bv0));
            h0.y = __float2half_rn(tanh_acc(acc[i][j][1] + bv1));
            h1.x = __float2half_rn(tanh_acc(acc[i][j][2] + bv0));
            h1.y = __float2half_rn(tanh_acc(acc[i][j][3] + bv1));
            *(__half2*)&C[(size_t)r0 * Ng + col]       = h0;
            *(__half2*)&C[(size_t)(r0 + 8) * Ng + col] = h1;
        }
    }
}

// ---------------------------------------------------------------------------
// merged prep:
//  blocks [0,8192):        A1 = fp16(x_a - 0.5)
//  blocks [8192,8448):     B1 tiles (transpose W1)
//  blocks [8448,12800):    B2 tiles (transpose W2, PERMUTED rows)
//  blocks [12800,12834):   b2p permute (8704 floats)
// ---------------------------------------------------------------------------
__global__ __launch_bounds__(256)
void prep_kernel(const float* __restrict__ x,
                 const float* __restrict__ W1, const float* __restrict__ W2,
                 const float* __restrict__ b2,
                 __half* __restrict__ A1, __half* __restrict__ B1,
                 __half* __restrict__ B2, float* __restrict__ b2p)
{
    const int bid = blockIdx.x;
    if (bid < 8192) {
        const int b = bid, s2 = threadIdx.x;
        const float2 v = *(const float2*)&x[(size_t)b * 1024 + s2 * 2];
        __half2 h;
        h.x = __float2half_rn(v.x - 0.5f);
        h.y = __float2half_rn(v.y - 0.5f);
        *(__half2*)&A1[(size_t)b * 512 + s2 * 2] = h;
        return;
    }
    if (bid >= 12800) {
        // permute bias2: b2p[(n%17)*512 + n/17] = b2[n]
        const int n = (bid - 12800) * 256 + threadIdx.x;
        if (n < NCC) b2p[(n % 17) * 512 + n / 17] = b2[n];
        return;
    }
    const bool isB1 = bid < 8448;
    const float* W = isB1 ? W1 : W2;
    const int Ncols = isB1 ? HH : NCC;
    const int local = isB1 ? bid - 8192 : bid - 8448;
    const int tilesN = Ncols / 32;
    const int n0 = (local % tilesN) * 32, k0 = (local / tilesN) * 32;

    __shared__ float t[32][33];
    const int tx = threadIdx.x & 31, ty = threadIdx.x >> 5;   // 32 x 8
    #pragma unroll
    for (int j = 0; j < 4; j++)
        t[ty + 8 * j][tx] = W[(size_t)(k0 + ty + 8 * j) * Ncols + n0 + tx];
    __syncthreads();
    #pragma unroll
    for (int j = 0; j < 4; j++) {
        const int n = n0 + ty + 8 * j;
        const int k = k0 + tx;
        const __half hv = __float2half_rn(t[tx][ty + 8 * j]);
        if (isB1) {
            B1[(size_t)n * 512 + k] = hv;
        } else {
            const int np = (n % 17) * 512 + (n / 17);   // permuted row
            B2[(size_t)np * 512 + k] = hv;
        }
    }
}

// ---------------------------------------------------------------------------
// spline epilogue — permuted net: v[j] = net[b][j*512 + s], fully coalesced,
// no smem staging. b-order reversed for L2 hits on the net tail.
// ---------------------------------------------------------------------------
__global__ __launch_bounds__(512)
void spline_epilogue_kernel(const float* __restrict__ x_input,
                            const float* __restrict__ log_density,
                            const __half* __restrict__ net,
                            float* __restrict__ out)
{
    __shared__ float red[16];

    const int b = BB - 1 - blockIdx.x;
    const int s = threadIdx.x;

    const __half* np = net + (size_t)b * NCC + s;
    float v[17];
    #pragma unroll
    for (int j = 0; j < 17; j++) v[j] = __half2float(np[(size_t)j * 512]);

    float m = v[9];
    #pragma unroll
    for (int j = 10; j < 17; j++) m = fmaxf(m, v[j]);
    float w[8]; float wsum = 0.f;
    #pragma unroll
    for (int j = 0; j < 8; j++) { w[j] = __expf(v[9 + j] - m); wsum += w[j]; }
    const float winv = 1.f / wsum;
    #pragma unroll
    for (int j = 0; j < 8; j++) w[j] *= winv;

    float eh[9];
    #pragma unroll
    for (int j = 0; j < 9; j++) eh[j] = __expf(v[j]);
    float denom = 0.f;
    #pragma unroll
    for (int i = 0; i < 8; i++) denom += 0.5f * w[i] * (eh[i] + eh[i + 1]);
    const float dinv = 1.f / denom;
    float h[9];
    #pragma unroll
    for (int i = 0; i < 9; i++) h[i] = eh[i] * dinv;

    const float xa = x_input[(size_t)b * 1024 + s];
    const float xb = x_input[(size_t)b * 1024 + 512 + s];

    int cnt = (-EPSK < xb) ? 1 : 0;
    float cs = 0.f;
    #pragma unroll
    for (int i = 0; i < 8; i++) { cs += w[i]; cnt += (cs < xb) ? 1 : 0; }
    int k = cnt - 1;
    k = k < 0 ? 0 : (k > 7 ? 7 : k);

    float xk = 0.f, pk = 0.f, wk = 0.f, hk = 0.f, hk1 = 0.f;
    #pragma unroll
    for (int i = 0; i < 8; i++) {
        const float area = 0.5f * w[i] * (h[i] + h[i + 1]);
        if (i < k)  { xk += w[i]; pk += area; }
        if (i == k) { wk = w[i]; hk = h[i]; hk1 = h[i + 1]; }
    }
    if (k == 0) xk = -EPSK;

    const float alpha = (xb - xk) / wk;
    const float phib  = pk + alpha * hk * wk + 0.5f * alpha * alpha * (hk1 - hk) * wk;
    const float lt    = __logf(fmaf(alpha, (hk1 - hk), hk));

    out[(size_t)b * 1024 + s]       = xa;
    out[(size_t)b * 1024 + 512 + s] = phib;

    float sum = lt;
    #pragma unroll
    for (int o = 16; o > 0; o >>= 1) sum += __shfl_xor_sync(0xffffffffu, sum, o);
    const int lane = s & 31, wid = s >> 5;
    if (lane == 0) red[wid] = sum;
    __syncthreads();
    if (s < 16) {
        float t = red[s];
        #pragma unroll
        for (int o = 8; o > 0; o >>= 1) t += __shfl_xor_sync(0xffffu, t, o);
        if (s == 0) out[(size_t)BB * 1024 + b] = log_density[b] - t;
    }
}

// ---------------------------------------------------------------------------
extern "C" void kernel_launch(void* const* d_in, const int* in_sizes, int n_in,
                              void* d_out, int out_size)
{
    const float* x  = (const float*)d_in[0];
    const float* ld = (const float*)d_in[1];
    const float* W1 = (const float*)d_in[2];
    const float* b1 = (const float*)d_in[3];
    const float* W2 = (const float*)d_in[4];
    const float* b2 = (const float*)d_in[5];
    float* out = (float*)d_out;

    __half *net, *A1, *A2, *B1, *B2;
    float* b2p;
    cudaGetSymbolAddress((void**)&net, g_net);
    cudaGetSymbolAddress((void**)&A1, g_A1);
    cudaGetSymbolAddress((void**)&A2, g_A2);
    cudaGetSymbolAddress((void**)&B1, g_B1);
    cudaGetSymbolAddress((void**)&B2, g_B2);
    cudaGetSymbolAddress((void**)&b2p, g_b2p);

    const int DS = 3 * 2 * 128 * 144;   // 110592
    cudaFuncSetAttribute((const void*)gemm_tc,
                         cudaFuncAttributeMaxDynamicSharedMemorySize, DS);

    // merged prep: 8192 split_x + 256 B1-tiles + 4352 B2-tiles + 34 bias-permute
    prep_kernel<<<8192 + 256 + 4352 + 34, 256>>>(x, W1, W2, b2, A1, B1, B2, b2p);

    // hid(fp16) = tanh((x_a-0.5) @ W1 + b1)
    gemm_tc<<<dim3(HH / 128, BB / 128), 256, DS>>>(A1, B1, b1, A2, 512);
    // net(fp16, permuted cols) = tanh(hid @ W2p + b2p)
    gemm_tc<<<dim3(NCC / 128, BB / 128), 256, DS>>>(A2, B2, b2p, net, NCC);

    spline_epilogue_kernel<<<BB, 512>>>(x, ld, net, out);
}

// round 17
// speedup vs baseline: 1.2037x; 1.0315x over previous
#include <cuda_runtime.h>
#include <cuda_fp16.h>
#include <stdint.h>
#include <math.h>

#define BB   8192
#define HH   512
#define NCC  8704          // S*(2K+1)
#define EPSK 1e-6f

// net layout PERMUTED: net[b][j*512 + s] = raw_net[b][s*17 + j]
__device__ __align__(128) __half g_net[(size_t)BB * NCC];   // 143 MB fp16
__device__ __align__(128) __half g_A1[(size_t)BB * 512];    // fp16(x_a - 0.5)
__device__ __align__(128) __half g_A2[(size_t)BB * 512];    // fp16(hid)
__device__ __align__(128) __half g_B1[(size_t)HH * 512];
__device__ __align__(128) __half g_B2[(size_t)NCC * 512];   // rows permuted
__device__ __align__(128) float  g_b2p[NCC];                // permuted bias2

// ------------------------------ helpers ------------------------------------
__device__ __forceinline__ uint32_t smem_u32(const void* p) {
    uint32_t a;
    asm("{ .reg .u64 t; cvta.to.shared.u64 t, %1; cvt.u32.u64 %0, t; }" : "=r"(a) : "l"(p));
    return a;
}
#define CP16(dst, src) \
    asm volatile("cp.async.cg.shared.global [%0], [%1], 16;" :: "r"(dst), "l"(src))
#define CP16A(dst, src) \
    asm volatile("cp.async.ca.shared.global [%0], [%1], 16;" :: "r"(dst), "l"(src))
#define CP_COMMIT() asm volatile("cp.async.commit_group;" ::: "memory")
#define CP_WAIT1()  asm volatile("cp.async.wait_group 1;" ::: "memory")

__device__ __forceinline__ void ldm_x4(uint32_t* r, uint32_t addr) {
    asm volatile("ldmatrix.sync.aligned.m8n8.x4.shared.b16 {%0,%1,%2,%3}, [%4];"
                 : "=r"(r[0]), "=r"(r[1]), "=r"(r[2]), "=r"(r[3]) : "r"(addr));
}
__device__ __forceinline__ void mma16816(float* c, const uint32_t* a, const uint32_t* b) {
    asm volatile(
        "mma.sync.aligned.m16n8k16.row.col.f32.f16.f16.f32 "
        "{%0,%1,%2,%3}, {%4,%5,%6,%7}, {%8,%9}, {%0,%1,%2,%3};"
        : "+f"(c[0]), "+f"(c[1]), "+f"(c[2]), "+f"(c[3])
        : "r"(a[0]), "r"(a[1]), "r"(a[2]), "r"(a[3]), "r"(b[0]), "r"(b[1]));
}
__device__ __forceinline__ float tanh_acc(float x) {
    float y = fminf(fmaxf(2.0f * x, -60.0f), 60.0f);
    float t = __expf(y);
    return __fdividef(t - 1.0f, t + 1.0f);
}
__device__ __forceinline__ float tanh_fast(float x) {
    float y;
    asm("tanh.approx.f32 %0, %1;" : "=f"(y) : "f"(x));
    return y;
}

// ---------------------------------------------------------------------------
// C(fp16)[m][n] = tanh( sum_k A[m][k]*B[n][k] + bias[n] )  single-pass fp16.
// R13 skeleton: CTA 128x128, 8 warps, warp 64x32, BK=64, 3-stage cp.async,
// one barrier/iter, 2 CTAs/SM, frag double-buffer.
// APPROX: use MUFU tanh.approx in epilogue (GEMM2 only).
// ---------------------------------------------------------------------------
template <bool APPROX>
__global__ __launch_bounds__(256, 2)
void gemm_tc(const __half* __restrict__ A, const __half* __restrict__ Bm,
             const float* __restrict__ bias, __half* __restrict__ C, int Ng)
{
    constexpr int BKB  = 128;
    constexpr int ROWP = BKB + 16;          // 144
    constexpr uint32_t REG  = 128 * ROWP;   // 18432
    constexpr uint32_t STGS = 2 * REG;      // 36864
    constexpr int NIT  = 8;

    extern __shared__ char dyn[];
    const uint32_t dynB = smem_u32(dyn);
    const int tid  = threadIdx.x;
    const int lane = tid & 31, w = tid >> 5;
    const int warp_m = w & 1, warp_n = w >> 1;        // 2 x 4
    const int mBase = blockIdx.y * 128, nBase = blockIdx.x * 128;

    const char* Ag = (const char*)(A  + (size_t)mBase * 512);
    const char* Bg = (const char*)(Bm + (size_t)nBase * 512);

    const int lrow = tid >> 3;
    const int lch  = (tid & 7) * 16;

#define LOAD_STAGE(c) do {                                                        \
    const uint32_t _s = dynB + ((c) % 3) * STGS;                                  \
    const size_t _kb = (size_t)(c) * BKB;                                         \
    _Pragma("unroll")                                                             \
    for (int _h = 0; _h < 4; _h++) {                                              \
        const int _r = lrow + _h * 32;                                            \
        CP16A(_s + _r * ROWP + lch,      Ag + (size_t)_r * 1024 + _kb + lch);     \
        CP16(_s + REG + _r * ROWP + lch, Bg + (size_t)_r * 1024 + _kb + lch);     \
    }                                                                             \
} while (0)

    LOAD_STAGE(0); CP_COMMIT();
    LOAD_STAGE(1); CP_COMMIT();

    float acc[4][4][4];
    #pragma unroll
    for (int i = 0; i < 4; i++)
        #pragma unroll
        for (int j = 0; j < 4; j++)
            #pragma unroll
            for (int e = 0; e < 4; e++) acc[i][j][e] = 0.f;

    const int grp = lane >> 3, lr = lane & 7;
    const uint32_t aRow = (uint32_t)(warp_m * 64 + (grp & 1) * 8 + lr) * ROWP
                        + (grp >> 1) * 16;
    const uint32_t bRow = REG
                        + (uint32_t)(warp_n * 32 + (grp >> 1) * 8 + lr) * ROWP
                        + (grp & 1) * 16;

    uint32_t aF[2][4][4], bF[2][4][2];

#define LDFRAG(st, kk, bf) do {                                                   \
    const uint32_t _ak = (st) + (kk) * 32 + aRow;                                 \
    const uint32_t _bk = (st) + (kk) * 32 + bRow;                                 \
    _Pragma("unroll")                                                             \
    for (int _p = 0; _p < 2; _p++) {                                              \
        uint32_t _r[4];                                                           \
        ldm_x4(_r, _bk + _p * (16 * ROWP));                                       \
        bF[bf][_p * 2][0] = _r[0]; bF[bf][_p * 2][1] = _r[1];                     \
        bF[bf][_p * 2 + 1][0] = _r[2]; bF[bf][_p * 2 + 1][1] = _r[3];             \
    }                                                                             \
    _Pragma("unroll")                                                             \
    for (int _i = 0; _i < 4; _i++)                                                \
        ldm_x4(aF[bf][_i], _ak + _i * (16 * ROWP));                               \
} while (0)

#define DOMMA(bf)                                                                 \
    _Pragma("unroll")                                                             \
    for (int _i = 0; _i < 4; _i++)                                                \
        _Pragma("unroll")                                                         \
        for (int _j = 0; _j < 4; _j++)                                            \
            mma16816(acc[_i][_j], aF[bf][_i], bF[bf][_j]);

    #pragma unroll
    for (int c = 0; c < NIT; c++) {
        CP_WAIT1();
        __syncthreads();
        const uint32_t st = dynB + (c % 3) * STGS;
        LDFRAG(st, 0, 0);
        if (c + 2 < NIT) LOAD_STAGE(c + 2);
        CP_COMMIT();

        #pragma unroll
        for (int kk = 0; kk < 4; kk++) {
            if (kk < 3) LDFRAG(st, kk + 1, (kk + 1) & 1);
            DOMMA(kk & 1);
        }
    }
#undef LOAD_STAGE
#undef LDFRAG
#undef DOMMA

    #pragma unroll
    for (int j = 0; j < 4; j++) {
        const int col = nBase + warp_n * 32 + j * 8 + (lane & 3) * 2;
        const float bv0 = bias[col], bv1 = bias[col + 1];
        #pragma unroll
        for (int i = 0; i < 4; i++) {
            const int r0 = mBase + warp_m * 64 + i * 16 + (lane >> 2);
            float t00, t01, t10, t11;
            if (APPROX) {
                t00 = tanh_fast(acc[i][j][0] + bv0);
                t01 = tanh_fast(acc[i][j][1] + bv1);
                t10 = tanh_fast(acc[i][j][2] + bv0);
                t11 = tanh_fast(acc[i][j][3] + bv1);
            } else {
                t00 = tanh_acc(acc[i][j][0] + bv0);
                t01 = tanh_acc(acc[i][j][1] + bv1);
                t10 = tanh_acc(acc[i][j][2] + bv0);
                t11 = tanh_acc(acc[i][j][3] + bv1);
            }
            __half2 h0, h1;
            h0.x = __float2half_rn(t00); h0.y = __float2half_rn(t01);
            h1.x = __float2half_rn(t10); h1.y = __float2half_rn(t11);
            *(__half2*)&C[(size_t)r0 * Ng + col]       = h0;
            *(__half2*)&C[(size_t)(r0 + 8) * Ng + col] = h1;
        }
    }
}

// ---------------------------------------------------------------------------
// merged prep (unchanged from R16)
// ---------------------------------------------------------------------------
__global__ __launch_bounds__(256)
void prep_kernel(const float* __restrict__ x,
                 const float* __restrict__ W1, const float* __restrict__ W2,
                 const float* __restrict__ b2,
                 __half* __restrict__ A1, __half* __restrict__ B1,
                 __half* __restrict__ B2, float* __restrict__ b2p)
{
    const int bid = blockIdx.x;
    if (bid < 8192) {
        const int b = bid, s2 = threadIdx.x;
        const float2 v = *(const float2*)&x[(size_t)b * 1024 + s2 * 2];
        __half2 h;
        h.x = __float2half_rn(v.x - 0.5f);
        h.y = __float2half_rn(v.y - 0.5f);
        *(__half2*)&A1[(size_t)b * 512 + s2 * 2] = h;
        return;
    }
    if (bid >= 12800) {
        const int n = (bid - 12800) * 256 + threadIdx.x;
        if (n < NCC) b2p[(n % 17) * 512 + n / 17] = b2[n];
        return;
    }
    const bool isB1 = bid < 8448;
    const float* W = isB1 ? W1 : W2;
    const int Ncols = isB1 ? HH : NCC;
    const int local = isB1 ? bid - 8192 : bid - 8448;
    const int tilesN = Ncols / 32;
    const int n0 = (local % tilesN) * 32, k0 = (local / tilesN) * 32;

    __shared__ float t[32][33];
    const int tx = threadIdx.x & 31, ty = threadIdx.x >> 5;   // 32 x 8
    #pragma unroll
    for (int j = 0; j < 4; j++)
        t[ty + 8 * j][tx] = W[(size_t)(k0 + ty + 8 * j) * Ncols + n0 + tx];
    __syncthreads();
    #pragma unroll
    for (int j = 0; j < 4; j++) {
        const int n = n0 + ty + 8 * j;
        const int k = k0 + tx;
        const __half hv = __float2half_rn(t[tx][ty + 8 * j]);
        if (isB1) {
            B1[(size_t)n * 512 + k] = hv;
        } else {
            const int np = (n % 17) * 512 + (n / 17);
            B2[(size_t)np * 512 + k] = hv;
        }
    }
}

// ---------------------------------------------------------------------------
// spline epilogue — permuted net (coalesced), single fused select loop.
// ---------------------------------------------------------------------------
__global__ __launch_bounds__(512)
void spline_epilogue_kernel(const float* __restrict__ x_input,
                            const float* __restrict__ log_density,
                            const __half* __restrict__ net,
                            float* __restrict__ out)
{
    __shared__ float red[16];

    const int b = BB - 1 - blockIdx.x;
    const int s = threadIdx.x;

    const __half* np = net + (size_t)b * NCC + s;
    float v[17];
    #pragma unroll
    for (int j = 0; j < 17; j++) v[j] = __half2float(np[(size_t)j * 512]);

    float m = v[9];
    #pragma unroll
    for (int j = 10; j < 17; j++) m = fmaxf(m, v[j]);
    float w[8]; float wsum = 0.f;
    #pragma unroll
    for (int j = 0; j < 8; j++) { w[j] = __expf(v[9 + j] - m); wsum += w[j]; }
    const float winv = 1.f / wsum;
    #pragma unroll
    for (int j = 0; j < 8; j++) w[j] *= winv;

    float eh[9];
    #pragma unroll
    for (int j = 0; j < 9; j++) eh[j] = __expf(v[j]);
    float denom = 0.f;
    #pragma unroll
    for (int i = 0; i < 8; i++) denom += 0.5f * w[i] * (eh[i] + eh[i + 1]);
    const float dinv = 1.f / denom;
    float h[9];
    #pragma unroll
    for (int i = 0; i < 9; i++) h[i] = eh[i] * dinv;

    const float xa = x_input[(size_t)b * 1024 + s];
    const float xb = x_input[(size_t)b * 1024 + 512 + s];

    // fused bin-select: last i (1..7) with cumsum(w[0..i-1]) < xb, default 0.
    float cs = 0.f, pa = 0.f;
    float xk = -EPSK, pk = 0.f, wk = w[0], hk = h[0], hk1 = h[1];
    #pragma unroll
    for (int i = 1; i < 8; i++) {
        cs += w[i - 1];
        pa += 0.5f * w[i - 1] * (h[i - 1] + h[i]);
        if (cs < xb) { xk = cs; pk = pa; wk = w[i]; hk = h[i]; hk1 = h[i + 1]; }
    }

    const float alpha = (xb - xk) / wk;
    const float phib  = pk + alpha * hk * wk + 0.5f * alpha * alpha * (hk1 - hk) * wk;
    const float lt    = __logf(fmaf(alpha, (hk1 - hk), hk));

    out[(size_t)b * 1024 + s]       = xa;
    out[(size_t)b * 1024 + 512 + s] = phib;

    float sum = lt;
    #pragma unroll
    for (int o = 16; o > 0; o >>= 1) sum += __shfl_xor_sync(0xffffffffu, sum, o);
    const int lane = s & 31, wid = s >> 5;
    if (lane == 0) red[wid] = sum;
    __syncthreads();
    if (s < 16) {
        float t = red[s];
        #pragma unroll
        for (int o = 8; o > 0; o >>= 1) t += __shfl_xor_sync(0xffffu, t, o);
        if (s == 0) out[(size_t)BB * 1024 + b] = log_density[b] - t;
    }
}

// ---------------------------------------------------------------------------
extern "C" void kernel_launch(void* const* d_in, const int* in_sizes, int n_in,
                              void* d_out, int out_size)
{
    const float* x  = (const float*)d_in[0];
    const float* ld = (const float*)d_in[1];
    const float* W1 = (const float*)d_in[2];
    const float* b1 = (const float*)d_in[3];
    const float* W2 = (const float*)d_in[4];
    const float* b2 = (const float*)d_in[5];
    float* out = (float*)d_out;

    __half *net, *A1, *A2, *B1, *B2;
    float* b2p;
    cudaGetSymbolAddress((void**)&net, g_net);
    cudaGetSymbolAddress((void**)&A1, g_A1);
    cudaGetSymbolAddress((void**)&A2, g_A2);
    cudaGetSymbolAddress((void**)&B1, g_B1);
    cudaGetSymbolAddress((void**)&B2, g_B2);
    cudaGetSymbolAddress((void**)&b2p, g_b2p);

    const int DS = 3 * 2 * 128 * 144;   // 110592
    cudaFuncSetAttribute((const void*)gemm_tc<false>,
                         cudaFuncAttributeMaxDynamicSharedMemorySize, DS);
    cudaFuncSetAttribute((const void*)gemm_tc<true>,
                         cudaFuncAttributeMaxDynamicSharedMemorySize, DS);

    prep_kernel<<<8192 + 256 + 4352 + 34, 256>>>(x, W1, W2, b2, A1, B1, B2, b2p);

    // hid(fp16) = tanh((x_a-0.5) @ W1 + b1)  — accurate tanh
    gemm_tc<false><<<dim3(HH / 128, BB / 128), 256, DS>>>(A1, B1, b1, A2, 512);
    // net(fp16, permuted) = tanh(hid @ W2p + b2p) — MUFU tanh
    gemm_tc<true><<<dim3(NCC / 128, BB / 128), 256, DS>>>(A2, B2, b2p, net, NCC);

    spline_epilogue_kernel<<<BB, 512>>>(x, ld, net, out);
}